// round 3
// baseline (speedup 1.0000x reference)
#include <cuda_runtime.h>
#include <cuda_bf16.h>

// ---------------- problem constants (fixed by reference) ----------------
#define N_NODES 50000
#define N_EDGES 800000
#define IN_C    256
#define HID_C   64
#define OUT_C   256
#define HEADS   4
#define N_GRAPHS 50
#define NEG_SLOPE 0.2f
#define FEAT 256   // HEADS*HID_C == OUT_C == 256 everywhere

// ---------------- scratch (device globals; no allocation allowed) -------
__device__ float    g_bufA[N_NODES * FEAT];   // h1, later out2
__device__ float    g_bufB[N_NODES * FEAT];   // out1 (relu'd -> layer2 input)
__device__ float    g_bufC[N_NODES * FEAT];   // h2
__device__ float    g_asrc[N_NODES * HEADS];
__device__ float    g_adst[N_NODES * HEADS];
__device__ unsigned g_menc[N_NODES * HEADS];  // encoded float max
__device__ float    g_ssum[N_NODES * HEADS];  // softmax denominators
__device__ float    g_ex  [N_EDGES * HEADS];  // per-edge exp(e - m)
__device__ float    g_psum[N_GRAPHS * FEAT];  // pooled sums
__device__ float    g_cnt [N_GRAPHS];         // nodes per graph

// ---------------- helpers ----------------
__device__ __forceinline__ unsigned flipf(float f) {
    unsigned u = __float_as_uint(f);
    return u ^ ((unsigned)((int)u >> 31) | 0x80000000u);
}
__device__ __forceinline__ float unflipf(unsigned u) {
    return __uint_as_float(u ^ ((unsigned)((int)(~u) >> 31) | 0x80000000u));
}
__device__ __forceinline__ float lrelu(float v) { return v >= 0.f ? v : NEG_SLOPE * v; }

// ---------------- zero kernels (reference globals directly) -------------
__global__ void zero_edge_state() {
    int i = blockIdx.x * 256 + threadIdx.x;
    if (i < N_NODES * HEADS) { g_menc[i] = 0u; g_ssum[i] = 0.f; }
}
__global__ void zero_bufB() {
    int i = blockIdx.x * 256 + threadIdx.x;
    if (i < N_NODES * FEAT) g_bufB[i] = 0.f;
}
__global__ void zero_bufA() {
    int i = blockIdx.x * 256 + threadIdx.x;
    if (i < N_NODES * FEAT) g_bufA[i] = 0.f;
}
__global__ void zero_pool() {
    int i = blockIdx.x * 256 + threadIdx.x;
    if (i < N_GRAPHS * FEAT) g_psum[i] = 0.f;
    if (i < N_GRAPHS) g_cnt[i] = 0.f;
}

// ---------------- tiled SGEMM: C[M,256] = A[M,256] @ B[256,256] ---------
#define BM 64
#define BN 64
#define BK 16
__global__ void sgemm(const float* __restrict__ A, const float* __restrict__ B,
                      float* __restrict__ C, int M) {
    const int N = FEAT, K = FEAT;
    __shared__ float As[BK][BM + 4];
    __shared__ float Bs[BK][BN];
    int bm = blockIdx.y * BM;
    int bn = blockIdx.x * BN;
    int t  = threadIdx.x;           // 256 threads
    int tx = t & 15, ty = t >> 4;
    float acc[4][4] = {};
    int am = t >> 2;                // 0..63
    int ak = (t & 3) << 2;          // 0,4,8,12
    int bk = t >> 4;                // 0..15
    int bn4 = (t & 15) << 2;        // 0..60
    for (int k0 = 0; k0 < K; k0 += BK) {
        int row = bm + am;
        float4 a4 = make_float4(0.f, 0.f, 0.f, 0.f);
        if (row < M) a4 = *(const float4*)(A + (size_t)row * K + k0 + ak);
        As[ak + 0][am] = a4.x; As[ak + 1][am] = a4.y;
        As[ak + 2][am] = a4.z; As[ak + 3][am] = a4.w;
        float4 b4 = *(const float4*)(B + (size_t)(k0 + bk) * N + bn + bn4);
        *(float4*)&Bs[bk][bn4] = b4;
        __syncthreads();
#pragma unroll
        for (int k = 0; k < BK; k++) {
            float ra[4], rb[4];
#pragma unroll
            for (int i = 0; i < 4; i++) ra[i] = As[k][ty * 4 + i];
#pragma unroll
            for (int j = 0; j < 4; j++) rb[j] = Bs[k][tx * 4 + j];
#pragma unroll
            for (int i = 0; i < 4; i++)
#pragma unroll
                for (int j = 0; j < 4; j++)
                    acc[i][j] = fmaf(ra[i], rb[j], acc[i][j]);
        }
        __syncthreads();
    }
#pragma unroll
    for (int i = 0; i < 4; i++) {
        int row = bm + ty * 4 + i;
        if (row < M)
            *(float4*)(C + (size_t)row * N + bn + tx * 4) =
                make_float4(acc[i][0], acc[i][1], acc[i][2], acc[i][3]);
    }
}

// ---------------- attention scores --------------------------------------
// layer 1: H=4, C=64; one thread per (node, head)
__global__ void att_scores1(const float* __restrict__ h,
                            const float* __restrict__ att_src,
                            const float* __restrict__ att_dst) {
    int i = blockIdx.x * 256 + threadIdx.x;
    if (i >= N_NODES * HEADS) return;
    int hh = i & 3;
    const float* row = h + (size_t)(i >> 2) * FEAT + hh * HID_C;
    float s1 = 0.f, s2 = 0.f;
#pragma unroll 8
    for (int c = 0; c < HID_C; c++) {
        float v = row[c];
        s1 = fmaf(v, att_src[hh * HID_C + c], s1);
        s2 = fmaf(v, att_dst[hh * HID_C + c], s2);
    }
    g_asrc[i] = s1; g_adst[i] = s2;
}
// layer 2: H=1, C=256; one warp per node
__global__ void att_scores2(const float* __restrict__ h,
                            const float* __restrict__ att_src,
                            const float* __restrict__ att_dst) {
    int w = (blockIdx.x * blockDim.x + threadIdx.x) >> 5;
    int lane = threadIdx.x & 31;
    if (w >= N_NODES) return;
    const float* row = h + (size_t)w * FEAT;
    float s1 = 0.f, s2 = 0.f;
#pragma unroll
    for (int c = lane; c < FEAT; c += 32) {
        float v = row[c];
        s1 = fmaf(v, att_src[c], s1);
        s2 = fmaf(v, att_dst[c], s2);
    }
#pragma unroll
    for (int o = 16; o; o >>= 1) {
        s1 += __shfl_xor_sync(0xffffffffu, s1, o);
        s2 += __shfl_xor_sync(0xffffffffu, s2, o);
    }
    if (lane == 0) { g_asrc[w] = s1; g_adst[w] = s2; }
}

// ---------------- edge softmax passes -----------------------------------
template <int H>
__global__ void edge_max(const int* __restrict__ src, const int* __restrict__ dst) {
    int i = blockIdx.x * 256 + threadIdx.x;
    if (i >= N_EDGES * H) return;
    int e = i / H, hh = i % H;
    int s = src[e], d = dst[e];
    float v = lrelu(g_asrc[s * H + hh] + g_adst[d * H + hh]);
    atomicMax(g_menc + d * H + hh, flipf(v));
}
template <int H>
__global__ void edge_expsum(const int* __restrict__ src, const int* __restrict__ dst) {
    int i = blockIdx.x * 256 + threadIdx.x;
    if (i >= N_EDGES * H) return;
    int e = i / H, hh = i % H;
    int s = src[e], d = dst[e];
    float v = lrelu(g_asrc[s * H + hh] + g_adst[d * H + hh]);
    float ex = __expf(v - unflipf(g_menc[d * H + hh]));
    g_ex[i] = ex;
    atomicAdd(g_ssum + d * H + hh, ex);
}
// aggregation: one warp per edge, 256 channels as 64 float4, vector red
template <int H>
__global__ void edge_agg(const int* __restrict__ src, const int* __restrict__ dst,
                         const float* __restrict__ h, float* __restrict__ out) {
    int gw = (blockIdx.x * blockDim.x + threadIdx.x) >> 5;
    int lane = threadIdx.x & 31;
    if (gw >= N_EDGES) return;
    int s = src[gw], d = dst[gw];
    const float4* hrow = (const float4*)(h + (size_t)s * FEAT);
    float4* orow = (float4*)(out + (size_t)d * FEAT);
#pragma unroll
    for (int j = 0; j < 2; j++) {
        int f = lane + 32 * j;                      // float4 index 0..63
        int hh = (H == 1) ? 0 : (f >> 4);           // (f*4)/64 for H=4
        float alpha = g_ex[gw * H + hh] / g_ssum[d * H + hh];
        float4 v = hrow[f];
        float4 av = make_float4(v.x * alpha, v.y * alpha, v.z * alpha, v.w * alpha);
        atomicAdd(orow + f, av);                    // red.global.add.v4.f32 (sm_90+)
    }
}

// ---------------- bias + relu on bufB (layer1 out) -----------------------
__global__ void bias_relu_bufB(const float* __restrict__ b) {
    int i = blockIdx.x * 256 + threadIdx.x;
    if (i >= N_NODES * FEAT) return;
    float v = g_bufB[i] + b[i & (FEAT - 1)];
    g_bufB[i] = v > 0.f ? v : 0.f;
}

// ---------------- pooling -------------------------------------------------
__global__ void count_nodes(const int* __restrict__ batch) {
    int i = blockIdx.x * 256 + threadIdx.x;
    if (i < N_NODES) atomicAdd(&g_cnt[batch[i]], 1.0f);
}
#define NPB 128
__global__ void pool_sum(const float* __restrict__ out2, const float* __restrict__ b2,
                         const int* __restrict__ batch) {
    int c = threadIdx.x;                      // 256 channels
    int n0 = blockIdx.x * NPB;
    int n1 = n0 + NPB; if (n1 > N_NODES) n1 = N_NODES;
    if (n0 >= N_NODES) return;
    float bias = b2[c];
    float acc = 0.f;
    int curg = batch[n0];
    for (int n = n0; n < n1; n++) {
        int g = batch[n];
        if (g != curg) { atomicAdd(&g_psum[curg * FEAT + c], acc); acc = 0.f; curg = g; }
        float v = out2[(size_t)n * FEAT + c] + bias;
        acc += v > 0.f ? v : 0.f;
    }
    atomicAdd(&g_psum[curg * FEAT + c], acc);
}
__global__ void fc_out(const float* __restrict__ Wfc, const float* __restrict__ bfc,
                       float* __restrict__ out) {
    int g = blockIdx.x, c = threadIdx.x;      // 50 x 256
    __shared__ float p[FEAT];
    float inv = 1.f / fmaxf(g_cnt[g], 1.f);
    p[c] = g_psum[g * FEAT + c] * inv;
    __syncthreads();
    float acc = bfc[c];
#pragma unroll 8
    for (int k = 0; k < FEAT; k++) acc = fmaf(p[k], Wfc[k * FEAT + c], acc);
    out[g * FEAT + c] = fmaxf(acc, 0.f);
}

// ---------------- launch --------------------------------------------------
extern "C" void kernel_launch(void* const* d_in, const int* in_sizes, int n_in,
                              void* d_out, int out_size) {
    const float* x        = (const float*)d_in[0];
    const int*   ei       = (const int*)  d_in[1];   // [2, E]
    const int*   batch    = (const int*)  d_in[2];
    const float* W1       = (const float*)d_in[3];
    const float* att_src1 = (const float*)d_in[4];
    const float* att_dst1 = (const float*)d_in[5];
    const float* b1       = (const float*)d_in[6];
    const float* W2       = (const float*)d_in[7];
    const float* att_src2 = (const float*)d_in[8];
    const float* att_dst2 = (const float*)d_in[9];
    const float* b2       = (const float*)d_in[10];
    const float* Wfc      = (const float*)d_in[11];
    const float* bfc      = (const float*)d_in[12];
    float* out = (float*)d_out;

    const int* src = ei;
    const int* dst = ei + N_EDGES;

    float *pA, *pB, *pC;
    cudaGetSymbolAddress((void**)&pA, g_bufA);
    cudaGetSymbolAddress((void**)&pB, g_bufB);
    cudaGetSymbolAddress((void**)&pC, g_bufC);

    dim3 gemm_grid(FEAT / BN, (N_NODES + BM - 1) / BM);
    int nfBlocks   = (N_NODES * FEAT + 255) / 256;        // 50000
    int nhBlocks   = (N_NODES * HEADS + 255) / 256;       // 782
    int e4Blocks   = (N_EDGES * HEADS + 255) / 256;       // 12500
    int e1Blocks   = (N_EDGES + 255) / 256;               // 3125
    int aggBlocks  = (N_EDGES * 32 + 255) / 256;          // 100000 (warp/edge)

    // ---- layer 1 ----
    zero_edge_state<<<nhBlocks, 256>>>();
    zero_bufB<<<nfBlocks, 256>>>();
    sgemm<<<gemm_grid, 256>>>(x, W1, pA, N_NODES);             // h1 = x @ W1
    att_scores1<<<nhBlocks, 256>>>(pA, att_src1, att_dst1);
    edge_max<HEADS><<<e4Blocks, 256>>>(src, dst);
    edge_expsum<HEADS><<<e4Blocks, 256>>>(src, dst);
    edge_agg<HEADS><<<aggBlocks, 256>>>(src, dst, pA, pB);     // out1 in bufB
    bias_relu_bufB<<<nfBlocks, 256>>>(b1);

    // ---- layer 2 ----
    zero_edge_state<<<nhBlocks, 256>>>();
    zero_bufA<<<nfBlocks, 256>>>();
    sgemm<<<gemm_grid, 256>>>(pB, W2, pC, N_NODES);            // h2 = out1 @ W2
    att_scores2<<<(N_NODES * 32 + 255) / 256, 256>>>(pC, att_src2, att_dst2);
    edge_max<1><<<e1Blocks, 256>>>(src, dst);
    edge_expsum<1><<<e1Blocks, 256>>>(src, dst);
    edge_agg<1><<<aggBlocks, 256>>>(src, dst, pC, pA);         // out2 in bufA

    // ---- pool + fc ----
    zero_pool<<<(N_GRAPHS * FEAT + 255) / 256, 256>>>();
    count_nodes<<<(N_NODES + 255) / 256, 256>>>(batch);
    pool_sum<<<(N_NODES + NPB - 1) / NPB, 256>>>(pA, b2, batch);
    fc_out<<<N_GRAPHS, FEAT>>>(Wfc, bfc, out);
}

// round 6
// speedup vs baseline: 1.6423x; 1.6423x over previous
#include <cuda_runtime.h>
#include <cuda_bf16.h>
#include <cstdint>

// ---------------- problem constants ----------------
#define N_NODES 50000
#define N_EDGES 800000
#define HEADS   4
#define N_GRAPHS 50
#define NEG_SLOPE 0.2f
#define FEAT 256

// ---------------- scratch ----------------
__device__ float    g_bufA[N_NODES * FEAT];   // h1, later out2
__device__ float    g_bufB[N_NODES * FEAT];   // out1 (relu'd)
__device__ float    g_bufC[N_NODES * FEAT];   // h2
__device__ float    g_asrc[N_NODES * HEADS];
__device__ float    g_adst[N_NODES * HEADS];
__device__ unsigned g_deg [N_NODES];
__device__ unsigned g_rowptr[N_NODES + 1];
__device__ unsigned g_cursor[N_NODES];
__device__ int      g_csrc[N_EDGES];
__device__ unsigned g_bsum[256];
__device__ float    g_psum[N_GRAPHS * FEAT];
__device__ float    g_cnt [N_GRAPHS];
__device__ __nv_bfloat16 g_w1h[FEAT * FEAT], g_w1l[FEAT * FEAT];
__device__ __nv_bfloat16 g_w2h[FEAT * FEAT], g_w2l[FEAT * FEAT];

// ---------------- helpers ----------------
__device__ __forceinline__ float lrelu(float v) { return v >= 0.f ? v : NEG_SLOPE * v; }
__device__ __forceinline__ uint32_t pack_bf2(float a, float b) {
    // low half = a, high half = b (as bf16)
    uint32_t lo = (uint32_t)__bfloat16_as_ushort(__float2bfloat16(a));
    uint32_t hi = (uint32_t)__bfloat16_as_ushort(__float2bfloat16(b));
    return (hi << 16) | lo;
}

// ================= weight convert: W[K,N] fp32 -> Wt[n][k] bf16 hi/lo =====
__global__ void conv_w(const float* __restrict__ W, __nv_bfloat16* __restrict__ bh,
                       __nv_bfloat16* __restrict__ bl) {
    int i = blockIdx.x * 256 + threadIdx.x;          // 65536
    int k = i >> 8, n = i & 255;
    float v = W[i];
    __nv_bfloat16 h = __float2bfloat16(v);
    bh[n * 256 + k] = h;
    bl[n * 256 + k] = __float2bfloat16(v - __bfloat162float(h));
}

// ================= HMMA GEMM: C[M,256] = A[M,256] @ W =====================
// Split fp32 = hi(bf16) + lo(bf16); C = Ah*Bh + Ah*Bl + Al*Bh.
// Block tile 128(M) x 128(N), 8 warps as 2(m) x 4(n), warp tile 64x32.
// A staged in smem in FRAGMENT-PERMUTED layout:
//   per (fm_g in 0..7 [16-row groups], ks in 0..15 [k16 steps]) a 32-lane block;
//   lane l = g*4+t holds 16 B = {A[g][16ks+2t..+1], A[g+8][16ks+2t..+1],
//                                A[g][16ks+8+2t..+1], A[g+8][16ks+8+2t..+1]}
//   (exactly the mma.m16n8k16 row-major A fragment {a0,a1,a2,a3}).
// B fragments loaded directly from global [n][k] bf16 (L1-resident).

__device__ __forceinline__ void mma16816(float* c, const uint32_t* a, const uint32_t* b) {
    asm volatile(
        "mma.sync.aligned.m16n8k16.row.col.f32.bf16.bf16.f32 "
        "{%0,%1,%2,%3}, {%4,%5,%6,%7}, {%8,%9}, {%0,%1,%2,%3};"
        : "+f"(c[0]), "+f"(c[1]), "+f"(c[2]), "+f"(c[3])
        : "r"(a[0]), "r"(a[1]), "r"(a[2]), "r"(a[3]), "r"(b[0]), "r"(b[1]));
}

__global__ void __launch_bounds__(256, 1) gemm_mma(
    const float* __restrict__ A, const __nv_bfloat16* __restrict__ Bh,
    const __nv_bfloat16* __restrict__ Bl, float* __restrict__ C, int M) {
    extern __shared__ char sm[];
    uint32_t* Ahs = (uint32_t*)sm;                 // 64 KB (4096 uint4 = 16384 u32)
    uint32_t* Als = (uint32_t*)(sm + 65536);       // 64 KB

    int t = threadIdx.x;
    int warp = t >> 5, lane = t & 31;
    int g = lane >> 2, tg = lane & 3;
    int m0 = blockIdx.y * 128;
    int n0 = blockIdx.x * 128;

    // ---- stage A: warp w handles 16-row group w; loop over 16 k-steps ----
    {
        int r0 = m0 + warp * 16 + g;
        int r1 = r0 + 8;
        bool ok0 = r0 < M, ok1 = r1 < M;
        const float* A0 = A + (size_t)r0 * 256 + 2 * tg;
        const float* A1 = A + (size_t)r1 * 256 + 2 * tg;
#pragma unroll
        for (int ks = 0; ks < 16; ks++) {
            float2 f0 = ok0 ? *(const float2*)(A0 + 16 * ks)     : make_float2(0.f, 0.f);
            float2 f1 = ok1 ? *(const float2*)(A1 + 16 * ks)     : make_float2(0.f, 0.f);
            float2 f2 = ok0 ? *(const float2*)(A0 + 16 * ks + 8) : make_float2(0.f, 0.f);
            float2 f3 = ok1 ? *(const float2*)(A1 + 16 * ks + 8) : make_float2(0.f, 0.f);
            float h0x = __bfloat162float(__float2bfloat16(f0.x));
            float h0y = __bfloat162float(__float2bfloat16(f0.y));
            float h1x = __bfloat162float(__float2bfloat16(f1.x));
            float h1y = __bfloat162float(__float2bfloat16(f1.y));
            float h2x = __bfloat162float(__float2bfloat16(f2.x));
            float h2y = __bfloat162float(__float2bfloat16(f2.y));
            float h3x = __bfloat162float(__float2bfloat16(f3.x));
            float h3y = __bfloat162float(__float2bfloat16(f3.y));
            int idx = ((warp * 16 + ks) * 32 + lane) * 4;   // u32 index
            uint4 hv = make_uint4(pack_bf2(f0.x, f0.y), pack_bf2(f1.x, f1.y),
                                  pack_bf2(f2.x, f2.y), pack_bf2(f3.x, f3.y));
            uint4 lv = make_uint4(pack_bf2(f0.x - h0x, f0.y - h0y),
                                  pack_bf2(f1.x - h1x, f1.y - h1y),
                                  pack_bf2(f2.x - h2x, f2.y - h2y),
                                  pack_bf2(f3.x - h3x, f3.y - h3y));
            *(uint4*)(Ahs + idx) = hv;
            *(uint4*)(Als + idx) = lv;
        }
    }
    __syncthreads();

    // ---- mainloop ----
    int wm = warp & 1;           // 0..1 -> m offset wm*64
    int wn = warp >> 1;          // 0..3 -> n offset wn*32
    float acc[4][4][4];
#pragma unroll
    for (int i = 0; i < 4; i++)
#pragma unroll
        for (int j = 0; j < 4; j++)
#pragma unroll
            for (int q = 0; q < 4; q++) acc[i][j][q] = 0.f;

    const __nv_bfloat16* Bbase[3] = { Bh, Bl, Bh };
#pragma unroll
    for (int pass = 0; pass < 3; pass++) {
        const uint32_t* Asm = (pass == 2) ? Als : Ahs;
        const __nv_bfloat16* Bg = Bbase[pass];
#pragma unroll 4
        for (int ks = 0; ks < 16; ks++) {
            uint32_t b[4][2];
#pragma unroll
            for (int fn = 0; fn < 4; fn++) {
                int n = n0 + wn * 32 + fn * 8 + g;
                const uint32_t* bp = (const uint32_t*)(Bg + (size_t)n * 256 + 16 * ks + 2 * tg);
                b[fn][0] = bp[0];      // k = 16ks+2t, +1
                b[fn][1] = bp[4];      // k = 16ks+8+2t, +1
            }
#pragma unroll
            for (int fm = 0; fm < 4; fm++) {
                int fm_g = wm * 4 + fm;
                uint4 av = *(const uint4*)(Asm + ((fm_g * 16 + ks) * 32 + lane) * 4);
                uint32_t a[4] = { av.x, av.y, av.z, av.w };
#pragma unroll
                for (int fn = 0; fn < 4; fn++)
                    mma16816(acc[fm][fn], a, b[fn]);
            }
        }
    }

    // ---- epilogue ----
#pragma unroll
    for (int fm = 0; fm < 4; fm++) {
        int r0 = m0 + wm * 64 + fm * 16 + g;
        int r1 = r0 + 8;
#pragma unroll
        for (int fn = 0; fn < 4; fn++) {
            int col = n0 + wn * 32 + fn * 8 + 2 * tg;
            if (r0 < M)
                *(float2*)(C + (size_t)r0 * 256 + col) = make_float2(acc[fm][fn][0], acc[fm][fn][1]);
            if (r1 < M)
                *(float2*)(C + (size_t)r1 * 256 + col) = make_float2(acc[fm][fn][2], acc[fm][fn][3]);
        }
    }
}

// ================= attention scores (warp per node, coalesced) ============
template <int H>
__global__ void att_scores(const float* __restrict__ h, const float* __restrict__ as,
                           const float* __restrict__ ad) {
    int w = (blockIdx.x * blockDim.x + threadIdx.x) >> 5;
    int lane = threadIdx.x & 31;
    if (w >= N_NODES) return;
    const float4* r  = (const float4*)(h + (size_t)w * FEAT + lane * 8);
    const float4* av = (const float4*)(as + lane * 8);
    const float4* dv = (const float4*)(ad + lane * 8);
    float4 r0 = r[0], r1 = r[1];
    float4 a0 = av[0], a1 = av[1];
    float4 d0 = dv[0], d1 = dv[1];
    float s1 = r0.x * a0.x + r0.y * a0.y + r0.z * a0.z + r0.w * a0.w
             + r1.x * a1.x + r1.y * a1.y + r1.z * a1.z + r1.w * a1.w;
    float s2 = r0.x * d0.x + r0.y * d0.y + r0.z * d0.z + r0.w * d0.w
             + r1.x * d1.x + r1.y * d1.y + r1.z * d1.z + r1.w * d1.w;
    const int G = (H == 4) ? 8 : 32;                 // lanes per head group
#pragma unroll
    for (int o = G / 2; o; o >>= 1) {
        s1 += __shfl_xor_sync(0xffffffffu, s1, o);
        s2 += __shfl_xor_sync(0xffffffffu, s2, o);
    }
    if ((lane & (G - 1)) == 0) {
        int hh = (H == 4) ? (lane >> 3) : 0;
        g_asrc[w * H + hh] = s1;
        g_adst[w * H + hh] = s2;
    }
}

// ================= CSR build ==============================================
__global__ void zero_misc() {
    int i = blockIdx.x * 256 + threadIdx.x;
    if (i < N_NODES) g_deg[i] = 0u;
    if (i < N_GRAPHS * FEAT) g_psum[i] = 0.f;
    if (i < N_GRAPHS) g_cnt[i] = 0.f;
}
__global__ void hist_dst(const int* __restrict__ dst) {
    int e = blockIdx.x * 256 + threadIdx.x;
    if (e < N_EDGES) atomicAdd(&g_deg[dst[e]], 1u);
}
__global__ void scan1() {
    __shared__ unsigned s[256];
    int t = threadIdx.x, i = blockIdx.x * 256 + t;
    unsigned v = (i < N_NODES) ? g_deg[i] : 0u;
    s[t] = v; __syncthreads();
#pragma unroll
    for (int o = 1; o < 256; o <<= 1) {
        unsigned u = (t >= o) ? s[t - o] : 0u;
        __syncthreads();
        s[t] += u; __syncthreads();
    }
    if (i < N_NODES) g_rowptr[i + 1] = s[t];
    if (t == 255) g_bsum[blockIdx.x] = s[255];
}
__global__ void scan2(int nb) {
    __shared__ unsigned s[256];
    int t = threadIdx.x;
    unsigned v = (t < nb) ? g_bsum[t] : 0u;
    s[t] = v; __syncthreads();
#pragma unroll
    for (int o = 1; o < 256; o <<= 1) {
        unsigned u = (t >= o) ? s[t - o] : 0u;
        __syncthreads();
        s[t] += u; __syncthreads();
    }
    if (t < nb) g_bsum[t] = s[t] - v;                // exclusive
}
__global__ void scan3() {
    int i = blockIdx.x * 256 + threadIdx.x;
    if (i >= N_NODES) return;
    unsigned f = g_rowptr[i + 1] + g_bsum[i >> 8];
    g_rowptr[i + 1] = f;
    g_cursor[i] = f - g_deg[i];
    if (i == 0) g_rowptr[0] = 0u;
}
__global__ void scatter(const int* __restrict__ src, const int* __restrict__ dst) {
    int e = blockIdx.x * 256 + threadIdx.x;
    if (e >= N_EDGES) return;
    unsigned p = atomicAdd(&g_cursor[dst[e]], 1u);
    g_csrc[p] = src[e];
}

// ================= fused GAT aggregation (warp per dst node) ==============
template <int H>
__global__ void gat_gather(const float* __restrict__ h, float* __restrict__ out,
                           const float* __restrict__ bias) {
    int w = (blockIdx.x * blockDim.x + threadIdx.x) >> 5;
    int lane = threadIdx.x & 31;
    if (w >= N_NODES) return;
    int r0 = (int)g_rowptr[w], r1 = (int)g_rowptr[w + 1];
    int ch = lane * 8;
    int hh = (H == 4) ? (lane >> 3) : 0;
    float4 b0 = *(const float4*)(bias + ch);
    float4 b1 = *(const float4*)(bias + ch + 4);
    float4* op = (float4*)(out + (size_t)w * FEAT + ch);
    if (r0 == r1) {
        op[0] = make_float4(fmaxf(b0.x, 0.f), fmaxf(b0.y, 0.f), fmaxf(b0.z, 0.f), fmaxf(b0.w, 0.f));
        op[1] = make_float4(fmaxf(b1.x, 0.f), fmaxf(b1.y, 0.f), fmaxf(b1.z, 0.f), fmaxf(b1.w, 0.f));
        return;
    }
    float adl[H];
#pragma unroll
    for (int q = 0; q < H; q++) adl[q] = g_adst[w * H + q];
    // pass 1: max per head
    float mx[H];
#pragma unroll
    for (int q = 0; q < H; q++) mx[q] = -3.4e38f;
    for (int e = r0 + lane; e < r1; e += 32) {
        int s = g_csrc[e];
#pragma unroll
        for (int q = 0; q < H; q++)
            mx[q] = fmaxf(mx[q], lrelu(g_asrc[s * H + q] + adl[q]));
    }
#pragma unroll
    for (int q = 0; q < H; q++)
#pragma unroll
        for (int o = 16; o; o >>= 1)
            mx[q] = fmaxf(mx[q], __shfl_xor_sync(0xffffffffu, mx[q], o));
    // pass 2: sum of exp
    float sm[H];
#pragma unroll
    for (int q = 0; q < H; q++) sm[q] = 0.f;
    for (int e = r0 + lane; e < r1; e += 32) {
        int s = g_csrc[e];
#pragma unroll
        for (int q = 0; q < H; q++)
            sm[q] += __expf(lrelu(g_asrc[s * H + q] + adl[q]) - mx[q]);
    }
#pragma unroll
    for (int q = 0; q < H; q++)
#pragma unroll
        for (int o = 16; o; o >>= 1)
            sm[q] += __shfl_xor_sync(0xffffffffu, sm[q], o);
    // pass 3: whole warp per edge, weighted accumulate
    float inv = 1.f / sm[hh];
    float m_h = mx[hh];
    float ad_h = adl[hh];
    float4 a0 = make_float4(0.f, 0.f, 0.f, 0.f), a1 = a0;
    for (int e = r0; e < r1; e++) {
        int s = g_csrc[e];                            // broadcast load
        float alpha = __expf(lrelu(g_asrc[s * H + hh] + ad_h) - m_h) * inv;
        const float4* hr = (const float4*)(h + (size_t)s * FEAT + ch);
        float4 v0 = hr[0], v1 = hr[1];
        a0.x = fmaf(alpha, v0.x, a0.x); a0.y = fmaf(alpha, v0.y, a0.y);
        a0.z = fmaf(alpha, v0.z, a0.z); a0.w = fmaf(alpha, v0.w, a0.w);
        a1.x = fmaf(alpha, v1.x, a1.x); a1.y = fmaf(alpha, v1.y, a1.y);
        a1.z = fmaf(alpha, v1.z, a1.z); a1.w = fmaf(alpha, v1.w, a1.w);
    }
    op[0] = make_float4(fmaxf(a0.x + b0.x, 0.f), fmaxf(a0.y + b0.y, 0.f),
                        fmaxf(a0.z + b0.z, 0.f), fmaxf(a0.w + b0.w, 0.f));
    op[1] = make_float4(fmaxf(a1.x + b1.x, 0.f), fmaxf(a1.y + b1.y, 0.f),
                        fmaxf(a1.z + b1.z, 0.f), fmaxf(a1.w + b1.w, 0.f));
}

// ================= pooling + fc ===========================================
__global__ void count_nodes(const int* __restrict__ batch) {
    int i = blockIdx.x * 256 + threadIdx.x;
    if (i < N_NODES) atomicAdd(&g_cnt[batch[i]], 1.0f);
}
#define NPB 128
__global__ void pool_sum(const float* __restrict__ out2, const int* __restrict__ batch) {
    int c = threadIdx.x;
    int n0 = blockIdx.x * NPB;
    int n1 = n0 + NPB; if (n1 > N_NODES) n1 = N_NODES;
    if (n0 >= N_NODES) return;
    float acc = 0.f;
    int curg = batch[n0];
    for (int n = n0; n < n1; n++) {
        int g = batch[n];
        if (g != curg) { atomicAdd(&g_psum[curg * FEAT + c], acc); acc = 0.f; curg = g; }
        acc += out2[(size_t)n * FEAT + c];
    }
    atomicAdd(&g_psum[curg * FEAT + c], acc);
}
__global__ void fc_out(const float* __restrict__ Wfc, const float* __restrict__ bfc,
                       float* __restrict__ out) {
    int g = blockIdx.x, c = threadIdx.x;
    __shared__ float p[FEAT];
    float inv = 1.f / fmaxf(g_cnt[g], 1.f);
    p[c] = g_psum[g * FEAT + c] * inv;
    __syncthreads();
    float acc = bfc[c];
#pragma unroll 8
    for (int k = 0; k < FEAT; k++) acc = fmaf(p[k], Wfc[k * FEAT + c], acc);
    out[g * FEAT + c] = fmaxf(acc, 0.f);
}

// ================= launch =================================================
extern "C" void kernel_launch(void* const* d_in, const int* in_sizes, int n_in,
                              void* d_out, int out_size) {
    const float* x        = (const float*)d_in[0];
    const int*   ei       = (const int*)  d_in[1];
    const int*   batch    = (const int*)  d_in[2];
    const float* W1       = (const float*)d_in[3];
    const float* att_src1 = (const float*)d_in[4];
    const float* att_dst1 = (const float*)d_in[5];
    const float* b1       = (const float*)d_in[6];
    const float* W2       = (const float*)d_in[7];
    const float* att_src2 = (const float*)d_in[8];
    const float* att_dst2 = (const float*)d_in[9];
    const float* b2       = (const float*)d_in[10];
    const float* Wfc      = (const float*)d_in[11];
    const float* bfc      = (const float*)d_in[12];
    float* out = (float*)d_out;

    const int* src = ei;
    const int* dst = ei + N_EDGES;

    float *pA, *pB, *pC;
    __nv_bfloat16 *w1h, *w1l, *w2h, *w2l;
    cudaGetSymbolAddress((void**)&pA, g_bufA);
    cudaGetSymbolAddress((void**)&pB, g_bufB);
    cudaGetSymbolAddress((void**)&pC, g_bufC);
    cudaGetSymbolAddress((void**)&w1h, g_w1h);
    cudaGetSymbolAddress((void**)&w1l, g_w1l);
    cudaGetSymbolAddress((void**)&w2h, g_w2h);
    cudaGetSymbolAddress((void**)&w2l, g_w2l);

    const int DYN_SM = 131072;    // 2 x 64 KB permuted A (hi/lo)
    cudaFuncSetAttribute(gemm_mma, cudaFuncAttributeMaxDynamicSharedMemorySize, DYN_SM);

    int nBlocks    = (N_NODES + 255) / 256;               // 196
    int eBlocks    = (N_EDGES + 255) / 256;               // 3125
    int warpBlocks = (N_NODES * 32 + 255) / 256;          // 6250
    dim3 gemmGrid(2, (N_NODES + 127) / 128);              // (2, 391)

    // ---- CSR build (shared by both layers) ----
    zero_misc<<<nBlocks, 256>>>();
    hist_dst<<<eBlocks, 256>>>(dst);
    scan1<<<nBlocks, 256>>>();
    scan2<<<1, 256>>>(nBlocks);
    scan3<<<nBlocks, 256>>>();
    scatter<<<eBlocks, 256>>>(src, dst);
    count_nodes<<<nBlocks, 256>>>(batch);

    // ---- weight conversion ----
    conv_w<<<256, 256>>>(W1, w1h, w1l);
    conv_w<<<256, 256>>>(W2, w2h, w2l);

    // ---- layer 1 ----
    gemm_mma<<<gemmGrid, 256, DYN_SM>>>(x, w1h, w1l, pA, N_NODES);
    att_scores<HEADS><<<warpBlocks, 256>>>(pA, att_src1, att_dst1);
    gat_gather<HEADS><<<warpBlocks, 256>>>(pA, pB, b1);   // out1 (bias+relu fused)

    // ---- layer 2 ----
    gemm_mma<<<gemmGrid, 256, DYN_SM>>>(pB, w2h, w2l, pC, N_NODES);
    att_scores<1><<<warpBlocks, 256>>>(pC, att_src2, att_dst2);
    gat_gather<1><<<warpBlocks, 256>>>(pC, pA, b2);       // out2 (bias+relu fused)

    // ---- pool + fc ----
    pool_sum<<<(N_NODES + NPB - 1) / NPB, 256>>>(pA, batch);
    fc_out<<<N_GRAPHS, FEAT>>>(Wfc, bfc, out);
}

// round 7
// speedup vs baseline: 1.7690x; 1.0772x over previous
#include <cuda_runtime.h>
#include <cuda_bf16.h>
#include <cstdint>

// ---------------- problem constants ----------------
#define N_NODES 50000
#define N_EDGES 800000
#define HEADS   4
#define N_GRAPHS 50
#define NEG_SLOPE 0.2f
#define FEAT 256

// ---------------- scratch ----------------
__device__ float    g_bufA[N_NODES * FEAT];   // h1, later out2
__device__ float    g_bufB[N_NODES * FEAT];   // out1 (relu'd)
__device__ float    g_bufC[N_NODES * FEAT];   // h2
__device__ float    g_asrc[N_NODES * HEADS];
__device__ float    g_adst[N_NODES * HEADS];
__device__ unsigned g_deg [N_NODES];
__device__ unsigned g_rowptr[N_NODES + 1];
__device__ unsigned g_cursor[N_NODES];
__device__ int      g_csrc[N_EDGES];
__device__ unsigned g_bsum[256];
__device__ float    g_psum[N_GRAPHS * FEAT];
__device__ float    g_cnt [N_GRAPHS];
__device__ __nv_bfloat16 g_w1h[FEAT * FEAT], g_w1l[FEAT * FEAT];
__device__ __nv_bfloat16 g_w2h[FEAT * FEAT], g_w2l[FEAT * FEAT];

// ---------------- helpers ----------------
__device__ __forceinline__ float lrelu(float v) { return v >= 0.f ? v : NEG_SLOPE * v; }
__device__ __forceinline__ uint32_t pack_bf2(float a, float b) {
    uint32_t lo = (uint32_t)__bfloat16_as_ushort(__float2bfloat16(a));
    uint32_t hi = (uint32_t)__bfloat16_as_ushort(__float2bfloat16(b));
    return (hi << 16) | lo;
}

// ================= weight convert (both layers, one kernel) ===============
__global__ void conv_w2(const float* __restrict__ W1, const float* __restrict__ W2) {
    int i = blockIdx.x * 256 + threadIdx.x;          // 0..131071
    int j = i & 65535;
    int k = j >> 8, n = j & 255;
    if (i < 65536) {
        float v = W1[j];
        __nv_bfloat16 h = __float2bfloat16(v);
        g_w1h[n * 256 + k] = h;
        g_w1l[n * 256 + k] = __float2bfloat16(v - __bfloat162float(h));
    } else {
        float v = W2[j];
        __nv_bfloat16 h = __float2bfloat16(v);
        g_w2h[n * 256 + k] = h;
        g_w2l[n * 256 + k] = __float2bfloat16(v - __bfloat162float(h));
    }
}

// ================= HMMA GEMM + fused attention-score epilogue =============
// C[M,256] = A[M,256] @ W  (fp32 via bf16 hi/lo 3-pass split)
// Epilogue also computes a_src[n,h] = <C_row_head, att_src>, a_dst likewise,
// accumulated with spread atomicAdd into g_asrc/g_adst (pre-zeroed).
__device__ __forceinline__ void mma16816(float* c, const uint32_t* a, const uint32_t* b) {
    asm volatile(
        "mma.sync.aligned.m16n8k16.row.col.f32.bf16.bf16.f32 "
        "{%0,%1,%2,%3}, {%4,%5,%6,%7}, {%8,%9}, {%0,%1,%2,%3};"
        : "+f"(c[0]), "+f"(c[1]), "+f"(c[2]), "+f"(c[3])
        : "r"(a[0]), "r"(a[1]), "r"(a[2]), "r"(a[3]), "r"(b[0]), "r"(b[1]));
}

template <int H>
__global__ void __launch_bounds__(256, 1) gemm_mma(
    const float* __restrict__ A, const __nv_bfloat16* __restrict__ Bh,
    const __nv_bfloat16* __restrict__ Bl, float* __restrict__ C, int M,
    const float* __restrict__ att_s, const float* __restrict__ att_d) {
    extern __shared__ char sm[];
    uint32_t* Ahs = (uint32_t*)sm;                 // 64 KB
    uint32_t* Als = (uint32_t*)(sm + 65536);       // 64 KB

    int t = threadIdx.x;
    int warp = t >> 5, lane = t & 31;
    int g = lane >> 2, tg = lane & 3;
    int m0 = blockIdx.y * 128;
    int n0 = blockIdx.x * 128;

    // ---- stage A (fragment-permuted bf16 hi/lo) ----
    {
        int r0 = m0 + warp * 16 + g;
        int r1 = r0 + 8;
        bool ok0 = r0 < M, ok1 = r1 < M;
        const float* A0 = A + (size_t)r0 * 256 + 2 * tg;
        const float* A1 = A + (size_t)r1 * 256 + 2 * tg;
#pragma unroll
        for (int ks = 0; ks < 16; ks++) {
            float2 f0 = ok0 ? *(const float2*)(A0 + 16 * ks)     : make_float2(0.f, 0.f);
            float2 f1 = ok1 ? *(const float2*)(A1 + 16 * ks)     : make_float2(0.f, 0.f);
            float2 f2 = ok0 ? *(const float2*)(A0 + 16 * ks + 8) : make_float2(0.f, 0.f);
            float2 f3 = ok1 ? *(const float2*)(A1 + 16 * ks + 8) : make_float2(0.f, 0.f);
            float h0x = __bfloat162float(__float2bfloat16(f0.x));
            float h0y = __bfloat162float(__float2bfloat16(f0.y));
            float h1x = __bfloat162float(__float2bfloat16(f1.x));
            float h1y = __bfloat162float(__float2bfloat16(f1.y));
            float h2x = __bfloat162float(__float2bfloat16(f2.x));
            float h2y = __bfloat162float(__float2bfloat16(f2.y));
            float h3x = __bfloat162float(__float2bfloat16(f3.x));
            float h3y = __bfloat162float(__float2bfloat16(f3.y));
            int idx = ((warp * 16 + ks) * 32 + lane) * 4;
            uint4 hv = make_uint4(pack_bf2(f0.x, f0.y), pack_bf2(f1.x, f1.y),
                                  pack_bf2(f2.x, f2.y), pack_bf2(f3.x, f3.y));
            uint4 lv = make_uint4(pack_bf2(f0.x - h0x, f0.y - h0y),
                                  pack_bf2(f1.x - h1x, f1.y - h1y),
                                  pack_bf2(f2.x - h2x, f2.y - h2y),
                                  pack_bf2(f3.x - h3x, f3.y - h3y));
            *(uint4*)(Ahs + idx) = hv;
            *(uint4*)(Als + idx) = lv;
        }
    }
    __syncthreads();

    // ---- mainloop ----
    int wm = warp & 1;
    int wn = warp >> 1;
    float acc[4][4][4];
#pragma unroll
    for (int i = 0; i < 4; i++)
#pragma unroll
        for (int j = 0; j < 4; j++)
#pragma unroll
            for (int q = 0; q < 4; q++) acc[i][j][q] = 0.f;

    const __nv_bfloat16* Bbase[3] = { Bh, Bl, Bh };
#pragma unroll
    for (int pass = 0; pass < 3; pass++) {
        const uint32_t* Asm = (pass == 2) ? Als : Ahs;
        const __nv_bfloat16* Bg = Bbase[pass];
#pragma unroll 4
        for (int ks = 0; ks < 16; ks++) {
            uint32_t b[4][2];
#pragma unroll
            for (int fn = 0; fn < 4; fn++) {
                int n = n0 + wn * 32 + fn * 8 + g;
                const uint32_t* bp = (const uint32_t*)(Bg + (size_t)n * 256 + 16 * ks + 2 * tg);
                b[fn][0] = bp[0];
                b[fn][1] = bp[4];
            }
#pragma unroll
            for (int fm = 0; fm < 4; fm++) {
                int fm_g = wm * 4 + fm;
                uint4 av = *(const uint4*)(Asm + ((fm_g * 16 + ks) * 32 + lane) * 4);
                uint32_t a[4] = { av.x, av.y, av.z, av.w };
#pragma unroll
                for (int fn = 0; fn < 4; fn++)
                    mma16816(acc[fm][fn], a, b[fn]);
            }
        }
    }

    // ---- epilogue: store C ----
#pragma unroll
    for (int fm = 0; fm < 4; fm++) {
        int r0 = m0 + wm * 64 + fm * 16 + g;
        int r1 = r0 + 8;
#pragma unroll
        for (int fn = 0; fn < 4; fn++) {
            int col = n0 + wn * 32 + fn * 8 + 2 * tg;
            if (r0 < M)
                *(float2*)(C + (size_t)r0 * 256 + col) = make_float2(acc[fm][fn][0], acc[fm][fn][1]);
            if (r1 < M)
                *(float2*)(C + (size_t)r1 * 256 + col) = make_float2(acc[fm][fn][2], acc[fm][fn][3]);
        }
    }

    // ---- epilogue: fused attention scores ----
    float2 as2[4], ad2[4];
#pragma unroll
    for (int fn = 0; fn < 4; fn++) {
        int col = n0 + wn * 32 + fn * 8 + 2 * tg;
        as2[fn] = *(const float2*)(att_s + col);
        ad2[fn] = *(const float2*)(att_d + col);
    }
    int head = (H == 4) ? ((n0 + wn * 32) >> 6) : 0;
#pragma unroll
    for (int fm = 0; fm < 4; fm++) {
        int r0 = m0 + wm * 64 + fm * 16 + g;
        int r1 = r0 + 8;
        float s0 = 0.f, d0 = 0.f, s1 = 0.f, d1 = 0.f;
#pragma unroll
        for (int fn = 0; fn < 4; fn++) {
            s0 += acc[fm][fn][0] * as2[fn].x + acc[fm][fn][1] * as2[fn].y;
            d0 += acc[fm][fn][0] * ad2[fn].x + acc[fm][fn][1] * ad2[fn].y;
            s1 += acc[fm][fn][2] * as2[fn].x + acc[fm][fn][3] * as2[fn].y;
            d1 += acc[fm][fn][2] * ad2[fn].x + acc[fm][fn][3] * ad2[fn].y;
        }
#pragma unroll
        for (int o = 1; o <= 2; o <<= 1) {
            s0 += __shfl_xor_sync(0xffffffffu, s0, o);
            d0 += __shfl_xor_sync(0xffffffffu, d0, o);
            s1 += __shfl_xor_sync(0xffffffffu, s1, o);
            d1 += __shfl_xor_sync(0xffffffffu, d1, o);
        }
        if (tg == 0) {
            if (r0 < M) {
                atomicAdd(&g_asrc[r0 * H + head], s0);
                atomicAdd(&g_adst[r0 * H + head], d0);
            }
            if (r1 < M) {
                atomicAdd(&g_asrc[r1 * H + head], s1);
                atomicAdd(&g_adst[r1 * H + head], d1);
            }
        }
    }
}

// ================= CSR build ==============================================
__global__ void zero_misc() {
    int i = blockIdx.x * 256 + threadIdx.x;
    if (i < N_NODES) g_deg[i] = 0u;
    if (i < N_GRAPHS * FEAT) g_psum[i] = 0.f;
    if (i < N_GRAPHS) g_cnt[i] = 0.f;
}
__global__ void zero_att() {
    int i = blockIdx.x * 256 + threadIdx.x;
    if (i < N_NODES * HEADS) { g_asrc[i] = 0.f; g_adst[i] = 0.f; }
}
__global__ void hist_plus(const int* __restrict__ dst, const int* __restrict__ batch) {
    int i = blockIdx.x * 256 + threadIdx.x;
    if (i < N_EDGES) atomicAdd(&g_deg[dst[i]], 1u);
    if (i < N_NODES) atomicAdd(&g_cnt[batch[i]], 1.0f);
}
__global__ void scan1() {
    __shared__ unsigned s[256];
    int t = threadIdx.x, i = blockIdx.x * 256 + t;
    unsigned v = (i < N_NODES) ? g_deg[i] : 0u;
    s[t] = v; __syncthreads();
#pragma unroll
    for (int o = 1; o < 256; o <<= 1) {
        unsigned u = (t >= o) ? s[t - o] : 0u;
        __syncthreads();
        s[t] += u; __syncthreads();
    }
    if (i < N_NODES) g_rowptr[i + 1] = s[t];
    if (t == 255) g_bsum[blockIdx.x] = s[255];
}
__global__ void scan2(int nb) {
    __shared__ unsigned s[256];
    int t = threadIdx.x;
    unsigned v = (t < nb) ? g_bsum[t] : 0u;
    s[t] = v; __syncthreads();
#pragma unroll
    for (int o = 1; o < 256; o <<= 1) {
        unsigned u = (t >= o) ? s[t - o] : 0u;
        __syncthreads();
        s[t] += u; __syncthreads();
    }
    if (t < nb) g_bsum[t] = s[t] - v;                // exclusive
}
__global__ void scan3() {
    int i = blockIdx.x * 256 + threadIdx.x;
    if (i >= N_NODES) return;
    unsigned f = g_rowptr[i + 1] + g_bsum[i >> 8];
    g_rowptr[i + 1] = f;
    g_cursor[i] = f - g_deg[i];
    if (i == 0) g_rowptr[0] = 0u;
}
__global__ void scatter(const int* __restrict__ src, const int* __restrict__ dst) {
    int e = blockIdx.x * 256 + threadIdx.x;
    if (e >= N_EDGES) return;
    unsigned p = atomicAdd(&g_cursor[dst[e]], 1u);
    g_csrc[p] = src[e];
}

// ================= fused single-pass GAT aggregation ======================
// out[w] = relu( (sum_e ex_e * h[src_e]) / (sum_e ex_e) + bias ), ex = exp(lrelu(score))
// No max-subtraction (scores are O(1); exp safe in fp32; softmax invariant).
// Each lane's head is fixed -> lane-private sum_ex is already the head sum.
template <int H>
__global__ void gat_gather(const float* __restrict__ h, float* __restrict__ out,
                           const float* __restrict__ bias) {
    int w = (blockIdx.x * blockDim.x + threadIdx.x) >> 5;
    int lane = threadIdx.x & 31;
    if (w >= N_NODES) return;
    int r0 = (int)g_rowptr[w], r1 = (int)g_rowptr[w + 1];
    int ch = lane * 8;
    int hh = (H == 4) ? (lane >> 3) : 0;
    float4 b0 = *(const float4*)(bias + ch);
    float4 b1 = *(const float4*)(bias + ch + 4);
    float4* op = (float4*)(out + (size_t)w * FEAT + ch);
    if (r0 == r1) {
        op[0] = make_float4(fmaxf(b0.x, 0.f), fmaxf(b0.y, 0.f), fmaxf(b0.z, 0.f), fmaxf(b0.w, 0.f));
        op[1] = make_float4(fmaxf(b1.x, 0.f), fmaxf(b1.y, 0.f), fmaxf(b1.z, 0.f), fmaxf(b1.w, 0.f));
        return;
    }
    float ad_h = g_adst[w * H + hh];
    float4 a0 = make_float4(0.f, 0.f, 0.f, 0.f), a1 = a0;
    float sum_ex = 0.f;
    // software-pipelined edge loop: prefetch next (src, asrc) while gathering
    int s  = g_csrc[r0];
    float asv = g_asrc[s * H + hh];
    for (int e = r0; e < r1; e++) {
        int sn = 0; float asn = 0.f;
        if (e + 1 < r1) {
            sn  = g_csrc[e + 1];
            asn = g_asrc[sn * H + hh];
        }
        float ex = __expf(lrelu(asv + ad_h));
        sum_ex += ex;
        const float4* hr = (const float4*)(h + (size_t)s * FEAT + ch);
        float4 v0 = hr[0], v1 = hr[1];
        a0.x = fmaf(ex, v0.x, a0.x); a0.y = fmaf(ex, v0.y, a0.y);
        a0.z = fmaf(ex, v0.z, a0.z); a0.w = fmaf(ex, v0.w, a0.w);
        a1.x = fmaf(ex, v1.x, a1.x); a1.y = fmaf(ex, v1.y, a1.y);
        a1.z = fmaf(ex, v1.z, a1.z); a1.w = fmaf(ex, v1.w, a1.w);
        s = sn; asv = asn;
    }
    float inv = 1.f / sum_ex;
    op[0] = make_float4(fmaxf(fmaf(a0.x, inv, b0.x), 0.f), fmaxf(fmaf(a0.y, inv, b0.y), 0.f),
                        fmaxf(fmaf(a0.z, inv, b0.z), 0.f), fmaxf(fmaf(a0.w, inv, b0.w), 0.f));
    op[1] = make_float4(fmaxf(fmaf(a1.x, inv, b1.x), 0.f), fmaxf(fmaf(a1.y, inv, b1.y), 0.f),
                        fmaxf(fmaf(a1.z, inv, b1.z), 0.f), fmaxf(fmaf(a1.w, inv, b1.w), 0.f));
}

// ================= pooling + fc ===========================================
#define NPB 128
__global__ void pool_sum(const float* __restrict__ out2, const int* __restrict__ batch) {
    int c = threadIdx.x;
    int n0 = blockIdx.x * NPB;
    int n1 = n0 + NPB; if (n1 > N_NODES) n1 = N_NODES;
    if (n0 >= N_NODES) return;
    float acc = 0.f;
    int curg = batch[n0];
    for (int n = n0; n < n1; n++) {
        int g = batch[n];
        if (g != curg) { atomicAdd(&g_psum[curg * FEAT + c], acc); acc = 0.f; curg = g; }
        acc += out2[(size_t)n * FEAT + c];
    }
    atomicAdd(&g_psum[curg * FEAT + c], acc);
}
__global__ void fc_out(const float* __restrict__ Wfc, const float* __restrict__ bfc,
                       float* __restrict__ out) {
    int g = blockIdx.x, c = threadIdx.x;
    __shared__ float p[FEAT];
    float inv = 1.f / fmaxf(g_cnt[g], 1.f);
    p[c] = g_psum[g * FEAT + c] * inv;
    __syncthreads();
    float acc = bfc[c];
#pragma unroll 8
    for (int k = 0; k < FEAT; k++) acc = fmaf(p[k], Wfc[k * FEAT + c], acc);
    out[g * FEAT + c] = fmaxf(acc, 0.f);
}

// ================= launch =================================================
extern "C" void kernel_launch(void* const* d_in, const int* in_sizes, int n_in,
                              void* d_out, int out_size) {
    const float* x        = (const float*)d_in[0];
    const int*   ei       = (const int*)  d_in[1];
    const int*   batch    = (const int*)  d_in[2];
    const float* W1       = (const float*)d_in[3];
    const float* att_src1 = (const float*)d_in[4];
    const float* att_dst1 = (const float*)d_in[5];
    const float* b1       = (const float*)d_in[6];
    const float* W2       = (const float*)d_in[7];
    const float* att_src2 = (const float*)d_in[8];
    const float* att_dst2 = (const float*)d_in[9];
    const float* b2       = (const float*)d_in[10];
    const float* Wfc      = (const float*)d_in[11];
    const float* bfc      = (const float*)d_in[12];
    float* out = (float*)d_out;

    const int* src = ei;
    const int* dst = ei + N_EDGES;

    float *pA, *pB, *pC;
    __nv_bfloat16 *w1h, *w1l, *w2h, *w2l;
    cudaGetSymbolAddress((void**)&pA, g_bufA);
    cudaGetSymbolAddress((void**)&pB, g_bufB);
    cudaGetSymbolAddress((void**)&pC, g_bufC);
    cudaGetSymbolAddress((void**)&w1h, g_w1h);
    cudaGetSymbolAddress((void**)&w1l, g_w1l);
    cudaGetSymbolAddress((void**)&w2h, g_w2h);
    cudaGetSymbolAddress((void**)&w2l, g_w2l);

    const int DYN_SM = 131072;
    cudaFuncSetAttribute(gemm_mma<HEADS>, cudaFuncAttributeMaxDynamicSharedMemorySize, DYN_SM);
    cudaFuncSetAttribute(gemm_mma<1>,     cudaFuncAttributeMaxDynamicSharedMemorySize, DYN_SM);

    int nBlocks    = (N_NODES + 255) / 256;               // 196
    int eBlocks    = (N_EDGES + 255) / 256;               // 3125
    int nhBlocks   = (N_NODES * HEADS + 255) / 256;       // 782
    int warpBlocks = (N_NODES * 32 + 255) / 256;          // 6250
    dim3 gemmGrid(2, (N_NODES + 127) / 128);              // (2, 391)

    // ---- CSR build + misc init ----
    zero_misc<<<nBlocks, 256>>>();
    hist_plus<<<eBlocks, 256>>>(dst, batch);
    scan1<<<nBlocks, 256>>>();
    scan2<<<1, 256>>>(nBlocks);
    scan3<<<nBlocks, 256>>>();
    scatter<<<eBlocks, 256>>>(src, dst);
    conv_w2<<<512, 256>>>(W1, W2);

    // ---- layer 1 ----
    zero_att<<<nhBlocks, 256>>>();
    gemm_mma<HEADS><<<gemmGrid, 256, DYN_SM>>>(x, w1h, w1l, pA, N_NODES, att_src1, att_dst1);
    gat_gather<HEADS><<<warpBlocks, 256>>>(pA, pB, b1);   // out1 (bias+relu fused)

    // ---- layer 2 ----
    zero_att<<<nhBlocks, 256>>>();
    gemm_mma<1><<<gemmGrid, 256, DYN_SM>>>(pB, w2h, w2l, pC, N_NODES, att_src2, att_dst2);
    gat_gather<1><<<warpBlocks, 256>>>(pC, pA, b2);       // out2 (bias+relu fused)

    // ---- pool + fc ----
    pool_sum<<<(N_NODES + NPB - 1) / NPB, 256>>>(pA, batch);
    fc_out<<<N_GRAPHS, FEAT>>>(Wfc, bfc, out);
}

// round 9
// speedup vs baseline: 1.8912x; 1.0691x over previous
#include <cuda_runtime.h>
#include <cuda_bf16.h>
#include <cuda_fp16.h>
#include <cstdint>

// ---------------- problem constants ----------------
#define N_NODES 50000
#define N_EDGES 800000
#define HEADS   4
#define N_GRAPHS 50
#define NEG_SLOPE 0.2f
#define FEAT 256

// ---------------- scratch ----------------
__device__ float    g_bufA[N_NODES * FEAT];   // out2
__device__ float    g_bufB[N_NODES * FEAT];   // out1 (relu'd)
__device__ __half   g_h16 [N_NODES * FEAT];   // h1, then h2 (fp16 gather payload)
__device__ float    g_asrc[N_NODES * HEADS];
__device__ float    g_adst[N_NODES * HEADS];
__device__ unsigned g_deg [N_NODES];
__device__ unsigned g_rowptr[N_NODES + 1];
__device__ unsigned g_cursor[N_NODES];
__device__ int      g_csrc[N_EDGES];
__device__ unsigned g_bsum[256];
__device__ float    g_psum[N_GRAPHS * FEAT];
__device__ float    g_cnt [N_GRAPHS];
__device__ __nv_bfloat16 g_w1h[FEAT * FEAT], g_w1l[FEAT * FEAT];
__device__ __nv_bfloat16 g_w2h[FEAT * FEAT], g_w2l[FEAT * FEAT];

// ---------------- helpers ----------------
__device__ __forceinline__ float lrelu(float v) { return v >= 0.f ? v : NEG_SLOPE * v; }
__device__ __forceinline__ uint32_t pack_bf2(float a, float b) {
    uint32_t lo = (uint32_t)__bfloat16_as_ushort(__float2bfloat16(a));
    uint32_t hi = (uint32_t)__bfloat16_as_ushort(__float2bfloat16(b));
    return (hi << 16) | lo;
}

// ================= weight convert (both layers, one kernel) ===============
__global__ void conv_w2(const float* __restrict__ W1, const float* __restrict__ W2) {
    int i = blockIdx.x * 256 + threadIdx.x;          // 0..131071
    int j = i & 65535;
    int k = j >> 8, n = j & 255;
    if (i < 65536) {
        float v = W1[j];
        __nv_bfloat16 h = __float2bfloat16(v);
        g_w1h[n * 256 + k] = h;
        g_w1l[n * 256 + k] = __float2bfloat16(v - __bfloat162float(h));
    } else {
        float v = W2[j];
        __nv_bfloat16 h = __float2bfloat16(v);
        g_w2h[n * 256 + k] = h;
        g_w2l[n * 256 + k] = __float2bfloat16(v - __bfloat162float(h));
    }
}

// ================= HMMA GEMM + fused attention-score epilogue =============
// C[M,256] (stored fp16) = A[M,256] fp32 @ W (bf16 hi/lo 3-pass split).
// Epilogue also computes a_src[n,h] = <C_row_head, att_src>, a_dst likewise
// (in fp32 from accumulators), accumulated via atomicAdd (pre-zeroed).
__device__ __forceinline__ void mma16816(float* c, const uint32_t* a, const uint32_t* b) {
    asm volatile(
        "mma.sync.aligned.m16n8k16.row.col.f32.bf16.bf16.f32 "
        "{%0,%1,%2,%3}, {%4,%5,%6,%7}, {%8,%9}, {%0,%1,%2,%3};"
        : "+f"(c[0]), "+f"(c[1]), "+f"(c[2]), "+f"(c[3])
        : "r"(a[0]), "r"(a[1]), "r"(a[2]), "r"(a[3]), "r"(b[0]), "r"(b[1]));
}

template <int H>
__global__ void __launch_bounds__(256, 1) gemm_mma(
    const float* __restrict__ A, const __nv_bfloat16* __restrict__ Bh,
    const __nv_bfloat16* __restrict__ Bl, __half* __restrict__ C, int M,
    const float* __restrict__ att_s, const float* __restrict__ att_d) {
    extern __shared__ char sm[];
    uint32_t* Ahs = (uint32_t*)sm;                 // 64 KB
    uint32_t* Als = (uint32_t*)(sm + 65536);       // 64 KB

    int t = threadIdx.x;
    int warp = t >> 5, lane = t & 31;
    int g = lane >> 2, tg = lane & 3;
    int m0 = blockIdx.y * 128;
    int n0 = blockIdx.x * 128;

    // ---- stage A (fragment-permuted bf16 hi/lo) ----
    {
        int r0 = m0 + warp * 16 + g;
        int r1 = r0 + 8;
        bool ok0 = r0 < M, ok1 = r1 < M;
        const float* A0 = A + (size_t)r0 * 256 + 2 * tg;
        const float* A1 = A + (size_t)r1 * 256 + 2 * tg;
#pragma unroll
        for (int ks = 0; ks < 16; ks++) {
            float2 f0 = ok0 ? *(const float2*)(A0 + 16 * ks)     : make_float2(0.f, 0.f);
            float2 f1 = ok1 ? *(const float2*)(A1 + 16 * ks)     : make_float2(0.f, 0.f);
            float2 f2 = ok0 ? *(const float2*)(A0 + 16 * ks + 8) : make_float2(0.f, 0.f);
            float2 f3 = ok1 ? *(const float2*)(A1 + 16 * ks + 8) : make_float2(0.f, 0.f);
            float h0x = __bfloat162float(__float2bfloat16(f0.x));
            float h0y = __bfloat162float(__float2bfloat16(f0.y));
            float h1x = __bfloat162float(__float2bfloat16(f1.x));
            float h1y = __bfloat162float(__float2bfloat16(f1.y));
            float h2x = __bfloat162float(__float2bfloat16(f2.x));
            float h2y = __bfloat162float(__float2bfloat16(f2.y));
            float h3x = __bfloat162float(__float2bfloat16(f3.x));
            float h3y = __bfloat162float(__float2bfloat16(f3.y));
            int idx = ((warp * 16 + ks) * 32 + lane) * 4;
            uint4 hv = make_uint4(pack_bf2(f0.x, f0.y), pack_bf2(f1.x, f1.y),
                                  pack_bf2(f2.x, f2.y), pack_bf2(f3.x, f3.y));
            uint4 lv = make_uint4(pack_bf2(f0.x - h0x, f0.y - h0y),
                                  pack_bf2(f1.x - h1x, f1.y - h1y),
                                  pack_bf2(f2.x - h2x, f2.y - h2y),
                                  pack_bf2(f3.x - h3x, f3.y - h3y));
            *(uint4*)(Ahs + idx) = hv;
            *(uint4*)(Als + idx) = lv;
        }
    }
    __syncthreads();

    // ---- mainloop ----
    int wm = warp & 1;
    int wn = warp >> 1;
    float acc[4][4][4];
#pragma unroll
    for (int i = 0; i < 4; i++)
#pragma unroll
        for (int j = 0; j < 4; j++)
#pragma unroll
            for (int q = 0; q < 4; q++) acc[i][j][q] = 0.f;

    const __nv_bfloat16* Bbase[3] = { Bh, Bl, Bh };
#pragma unroll
    for (int pass = 0; pass < 3; pass++) {
        const uint32_t* Asm = (pass == 2) ? Als : Ahs;
        const __nv_bfloat16* Bg = Bbase[pass];
#pragma unroll 4
        for (int ks = 0; ks < 16; ks++) {
            uint32_t b[4][2];
#pragma unroll
            for (int fn = 0; fn < 4; fn++) {
                int n = n0 + wn * 32 + fn * 8 + g;
                const uint32_t* bp = (const uint32_t*)(Bg + (size_t)n * 256 + 16 * ks + 2 * tg);
                b[fn][0] = bp[0];
                b[fn][1] = bp[4];
            }
#pragma unroll
            for (int fm = 0; fm < 4; fm++) {
                int fm_g = wm * 4 + fm;
                uint4 av = *(const uint4*)(Asm + ((fm_g * 16 + ks) * 32 + lane) * 4);
                uint32_t a[4] = { av.x, av.y, av.z, av.w };
#pragma unroll
                for (int fn = 0; fn < 4; fn++)
                    mma16816(acc[fm][fn], a, b[fn]);
            }
        }
    }

    // ---- epilogue: store C as fp16 ----
#pragma unroll
    for (int fm = 0; fm < 4; fm++) {
        int r0 = m0 + wm * 64 + fm * 16 + g;
        int r1 = r0 + 8;
#pragma unroll
        for (int fn = 0; fn < 4; fn++) {
            int col = n0 + wn * 32 + fn * 8 + 2 * tg;
            if (r0 < M)
                *(__half2*)(C + (size_t)r0 * 256 + col) =
                    __floats2half2_rn(acc[fm][fn][0], acc[fm][fn][1]);
            if (r1 < M)
                *(__half2*)(C + (size_t)r1 * 256 + col) =
                    __floats2half2_rn(acc[fm][fn][2], acc[fm][fn][3]);
        }
    }

    // ---- epilogue: fused attention scores (fp32 accumulators) ----
    float2 as2[4], ad2[4];
#pragma unroll
    for (int fn = 0; fn < 4; fn++) {
        int col = n0 + wn * 32 + fn * 8 + 2 * tg;
        as2[fn] = *(const float2*)(att_s + col);
        ad2[fn] = *(const float2*)(att_d + col);
    }
    int head = (H == 4) ? ((n0 + wn * 32) >> 6) : 0;
#pragma unroll
    for (int fm = 0; fm < 4; fm++) {
        int r0 = m0 + wm * 64 + fm * 16 + g;
        int r1 = r0 + 8;
        float s0 = 0.f, d0 = 0.f, s1 = 0.f, d1 = 0.f;
#pragma unroll
        for (int fn = 0; fn < 4; fn++) {
            s0 += acc[fm][fn][0] * as2[fn].x + acc[fm][fn][1] * as2[fn].y;
            d0 += acc[fm][fn][0] * ad2[fn].x + acc[fm][fn][1] * ad2[fn].y;
            s1 += acc[fm][fn][2] * as2[fn].x + acc[fm][fn][3] * as2[fn].y;
            d1 += acc[fm][fn][2] * ad2[fn].x + acc[fm][fn][3] * ad2[fn].y;
        }
#pragma unroll
        for (int o = 1; o <= 2; o <<= 1) {
            s0 += __shfl_xor_sync(0xffffffffu, s0, o);
            d0 += __shfl_xor_sync(0xffffffffu, d0, o);
            s1 += __shfl_xor_sync(0xffffffffu, s1, o);
            d1 += __shfl_xor_sync(0xffffffffu, d1, o);
        }
        if (tg == 0) {
            if (r0 < M) {
                atomicAdd(&g_asrc[r0 * H + head], s0);
                atomicAdd(&g_adst[r0 * H + head], d0);
            }
            if (r1 < M) {
                atomicAdd(&g_asrc[r1 * H + head], s1);
                atomicAdd(&g_adst[r1 * H + head], d1);
            }
        }
    }
}

// ================= CSR build ==============================================
__global__ void zero_misc() {
    int i = blockIdx.x * 256 + threadIdx.x;
    if (i < N_NODES) g_deg[i] = 0u;
    if (i < N_NODES * HEADS) { g_asrc[i] = 0.f; g_adst[i] = 0.f; }
    if (i < N_GRAPHS * FEAT) g_psum[i] = 0.f;
    if (i < N_GRAPHS) g_cnt[i] = 0.f;
}
__global__ void zero_att() {
    int i = blockIdx.x * 256 + threadIdx.x;
    if (i < N_NODES * HEADS) { g_asrc[i] = 0.f; g_adst[i] = 0.f; }
}
__global__ void hist_plus(const int* __restrict__ dst, const int* __restrict__ batch) {
    int i = blockIdx.x * 256 + threadIdx.x;
    if (i < N_EDGES) atomicAdd(&g_deg[dst[i]], 1u);
    if (i < N_NODES) atomicAdd(&g_cnt[batch[i]], 1.0f);
}
__global__ void scan1() {
    __shared__ unsigned s[256];
    int t = threadIdx.x, i = blockIdx.x * 256 + t;
    unsigned v = (i < N_NODES) ? g_deg[i] : 0u;
    s[t] = v; __syncthreads();
#pragma unroll
    for (int o = 1; o < 256; o <<= 1) {
        unsigned u = (t >= o) ? s[t - o] : 0u;
        __syncthreads();
        s[t] += u; __syncthreads();
    }
    if (i < N_NODES) g_rowptr[i + 1] = s[t];
    if (t == 255) g_bsum[blockIdx.x] = s[255];
}
__global__ void scan2(int nb) {
    __shared__ unsigned s[256];
    int t = threadIdx.x;
    unsigned v = (t < nb) ? g_bsum[t] : 0u;
    s[t] = v; __syncthreads();
#pragma unroll
    for (int o = 1; o < 256; o <<= 1) {
        unsigned u = (t >= o) ? s[t - o] : 0u;
        __syncthreads();
        s[t] += u; __syncthreads();
    }
    if (t < nb) g_bsum[t] = s[t] - v;                // exclusive
}
__global__ void scan3() {
    int i = blockIdx.x * 256 + threadIdx.x;
    if (i >= N_NODES) return;
    unsigned f = g_rowptr[i + 1] + g_bsum[i >> 8];
    g_rowptr[i + 1] = f;
    g_cursor[i] = f - g_deg[i];
    if (i == 0) g_rowptr[0] = 0u;
}
__global__ void scatter(const int* __restrict__ src, const int* __restrict__ dst) {
    int e = blockIdx.x * 256 + threadIdx.x;
    if (e >= N_EDGES) return;
    unsigned p = atomicAdd(&g_cursor[dst[e]], 1u);
    g_csrc[p] = src[e];
}

// ================= fused single-pass GAT aggregation ======================
// out[w] = relu( (sum_e ex_e * h[src_e]) / (sum_e ex_e) + bias ), ex = exp(lrelu(score))
// h is fp16 (one uint4 = 8 channels per lane per edge); accumulation in fp32.
template <int H>
__global__ void gat_gather(const __half* __restrict__ h, float* __restrict__ out,
                           const float* __restrict__ bias) {
    int w = (blockIdx.x * blockDim.x + threadIdx.x) >> 5;
    int lane = threadIdx.x & 31;
    if (w >= N_NODES) return;
    int r0 = (int)g_rowptr[w], r1 = (int)g_rowptr[w + 1];
    int ch = lane * 8;
    int hh = (H == 4) ? (lane >> 3) : 0;
    float4 b0 = *(const float4*)(bias + ch);
    float4 b1 = *(const float4*)(bias + ch + 4);
    float4* op = (float4*)(out + (size_t)w * FEAT + ch);
    if (r0 == r1) {
        op[0] = make_float4(fmaxf(b0.x, 0.f), fmaxf(b0.y, 0.f), fmaxf(b0.z, 0.f), fmaxf(b0.w, 0.f));
        op[1] = make_float4(fmaxf(b1.x, 0.f), fmaxf(b1.y, 0.f), fmaxf(b1.z, 0.f), fmaxf(b1.w, 0.f));
        return;
    }
    float ad_h = g_adst[w * H + hh];
    float acc[8];
#pragma unroll
    for (int q = 0; q < 8; q++) acc[q] = 0.f;
    float sum_ex = 0.f;
    // software-pipelined edge loop: prefetch next (src, asrc) while gathering
    int s  = g_csrc[r0];
    float asv = g_asrc[s * H + hh];
    for (int e = r0; e < r1; e++) {
        int sn = 0; float asn = 0.f;
        if (e + 1 < r1) {
            sn  = g_csrc[e + 1];
            asn = g_asrc[sn * H + hh];
        }
        float ex = __expf(lrelu(asv + ad_h));
        sum_ex += ex;
        uint4 v = *(const uint4*)(h + (size_t)s * FEAT + ch);   // 8 halves
        const __half2* hv = (const __half2*)&v;
#pragma unroll
        for (int q = 0; q < 4; q++) {
            float2 f = __half22float2(hv[q]);
            acc[2 * q + 0] = fmaf(ex, f.x, acc[2 * q + 0]);
            acc[2 * q + 1] = fmaf(ex, f.y, acc[2 * q + 1]);
        }
        s = sn; asv = asn;
    }
    float inv = 1.f / sum_ex;
    op[0] = make_float4(fmaxf(fmaf(acc[0], inv, b0.x), 0.f), fmaxf(fmaf(acc[1], inv, b0.y), 0.f),
                        fmaxf(fmaf(acc[2], inv, b0.z), 0.f), fmaxf(fmaf(acc[3], inv, b0.w), 0.f));
    op[1] = make_float4(fmaxf(fmaf(acc[4], inv, b1.x), 0.f), fmaxf(fmaf(acc[5], inv, b1.y), 0.f),
                        fmaxf(fmaf(acc[6], inv, b1.z), 0.f), fmaxf(fmaf(acc[7], inv, b1.w), 0.f));
}

// ================= pooling + fc ===========================================
#define NPB 128
__global__ void pool_sum(const float* __restrict__ out2, const int* __restrict__ batch) {
    int c = threadIdx.x;
    int n0 = blockIdx.x * NPB;
    int n1 = n0 + NPB; if (n1 > N_NODES) n1 = N_NODES;
    if (n0 >= N_NODES) return;
    float acc = 0.f;
    int curg = batch[n0];
    for (int n = n0; n < n1; n++) {
        int g = batch[n];
        if (g != curg) { atomicAdd(&g_psum[curg * FEAT + c], acc); acc = 0.f; curg = g; }
        acc += out2[(size_t)n * FEAT + c];
    }
    atomicAdd(&g_psum[curg * FEAT + c], acc);
}
__global__ void fc_out(const float* __restrict__ Wfc, const float* __restrict__ bfc,
                       float* __restrict__ out) {
    int g = blockIdx.x, c = threadIdx.x;
    __shared__ float p[FEAT];
    float inv = 1.f / fmaxf(g_cnt[g], 1.f);
    p[c] = g_psum[g * FEAT + c] * inv;
    __syncthreads();
    float acc = bfc[c];
#pragma unroll 8
    for (int k = 0; k < FEAT; k++) acc = fmaf(p[k], Wfc[k * FEAT + c], acc);
    out[g * FEAT + c] = fmaxf(acc, 0.f);
}

// ================= launch =================================================
extern "C" void kernel_launch(void* const* d_in, const int* in_sizes, int n_in,
                              void* d_out, int out_size) {
    const float* x        = (const float*)d_in[0];
    const int*   ei       = (const int*)  d_in[1];
    const int*   batch    = (const int*)  d_in[2];
    const float* W1       = (const float*)d_in[3];
    const float* att_src1 = (const float*)d_in[4];
    const float* att_dst1 = (const float*)d_in[5];
    const float* b1       = (const float*)d_in[6];
    const float* W2       = (const float*)d_in[7];
    const float* att_src2 = (const float*)d_in[8];
    const float* att_dst2 = (const float*)d_in[9];
    const float* b2       = (const float*)d_in[10];
    const float* Wfc      = (const float*)d_in[11];
    const float* bfc      = (const float*)d_in[12];
    float* out = (float*)d_out;

    const int* src = ei;
    const int* dst = ei + N_EDGES;

    float *pA, *pB;
    __half* ph;
    __nv_bfloat16 *w1h, *w1l, *w2h, *w2l;
    cudaGetSymbolAddress((void**)&pA, g_bufA);
    cudaGetSymbolAddress((void**)&pB, g_bufB);
    cudaGetSymbolAddress((void**)&ph, g_h16);
    cudaGetSymbolAddress((void**)&w1h, g_w1h);
    cudaGetSymbolAddress((void**)&w1l, g_w1l);
    cudaGetSymbolAddress((void**)&w2h, g_w2h);
    cudaGetSymbolAddress((void**)&w2l, g_w2l);

    const int DYN_SM = 131072;
    cudaFuncSetAttribute(gemm_mma<HEADS>, cudaFuncAttributeMaxDynamicSharedMemorySize, DYN_SM);
    cudaFuncSetAttribute(gemm_mma<1>,     cudaFuncAttributeMaxDynamicSharedMemorySize, DYN_SM);

    int eBlocks    = (N_EDGES + 255) / 256;               // 3125
    int nhBlocks   = (N_NODES * HEADS + 255) / 256;       // 782
    int warpBlocks = (N_NODES * 32 + 255) / 256;          // 6250
    dim3 gemmGrid(2, (N_NODES + 127) / 128);              // (2, 391)

    // ---- CSR build + misc init (zero_misc also zeroes layer-1 att bufs) ----
    zero_misc<<<nhBlocks, 256>>>();
    hist_plus<<<eBlocks, 256>>>(dst, batch);
    scan1<<<(N_NODES + 255) / 256, 256>>>();
    scan2<<<1, 256>>>((N_NODES + 255) / 256);
    scan3<<<(N_NODES + 255) / 256, 256>>>();
    scatter<<<eBlocks, 256>>>(src, dst);
    conv_w2<<<512, 256>>>(W1, W2);

    // ---- layer 1 ----
    gemm_mma<HEADS><<<gemmGrid, 256, DYN_SM>>>(x, w1h, w1l, ph, N_NODES, att_src1, att_dst1);
    gat_gather<HEADS><<<warpBlocks, 256>>>(ph, pB, b1);   // out1 (bias+relu fused)

    // ---- layer 2 ----
    zero_att<<<nhBlocks, 256>>>();
    gemm_mma<1><<<gemmGrid, 256, DYN_SM>>>(pB, w2h, w2l, ph, N_NODES, att_src2, att_dst2);
    gat_gather<1><<<warpBlocks, 256>>>(ph, pA, b2);       // out2 (bias+relu fused)

    // ---- pool + fc ----
    pool_sum<<<(N_NODES + NPB - 1) / NPB, 256>>>(pA, batch);
    fc_out<<<N_GRAPHS, FEAT>>>(Wfc, bfc, out);
}

// round 11
// speedup vs baseline: 2.0073x; 1.0614x over previous
#include <cuda_runtime.h>
#include <cuda_bf16.h>
#include <cuda_fp16.h>
#include <cstdint>

// ---------------- problem constants ----------------
#define N_NODES 50000
#define N_EDGES 800000
#define HEADS   4
#define N_GRAPHS 50
#define NEG_SLOPE 0.2f
#define FEAT 256

// ---------------- scratch ----------------
__device__ float    g_bufA[N_NODES * FEAT];   // out2
__device__ float    g_bufB[N_NODES * FEAT];   // out1 (relu'd)
__device__ __half   g_h16 [N_NODES * FEAT];   // h1, then h2 (fp16 gather payload)
__device__ float    g_asrc[N_NODES * HEADS];  // layer-1 scores
__device__ float    g_adst[N_NODES * HEADS];
__device__ float    g_asrc2[N_NODES];         // layer-2 scores (H=1)
__device__ float    g_adst2[N_NODES];
__device__ unsigned g_deg [N_NODES];
__device__ unsigned g_rowptr[N_NODES + 1];
__device__ unsigned g_cursor[N_NODES];
__device__ int      g_csrc[N_EDGES];
__device__ unsigned g_bsum[256];
__device__ float    g_psum[N_GRAPHS * FEAT];
__device__ float    g_cnt [N_GRAPHS];
__device__ __nv_bfloat16 g_w1h[FEAT * FEAT], g_w1l[FEAT * FEAT];
__device__ __nv_bfloat16 g_w2h[FEAT * FEAT], g_w2l[FEAT * FEAT];

// ---------------- helpers ----------------
__device__ __forceinline__ float lrelu(float v) { return v >= 0.f ? v : NEG_SLOPE * v; }
__device__ __forceinline__ uint32_t pack_bf2(float a, float b) {
    uint32_t lo = (uint32_t)__bfloat16_as_ushort(__float2bfloat16(a));
    uint32_t hi = (uint32_t)__bfloat16_as_ushort(__float2bfloat16(b));
    return (hi << 16) | lo;
}

// ================= weight convert (both layers, one kernel) ===============
__global__ void conv_w2(const float* __restrict__ W1, const float* __restrict__ W2) {
    int i = blockIdx.x * 256 + threadIdx.x;          // 0..131071
    int j = i & 65535;
    int k = j >> 8, n = j & 255;
    if (i < 65536) {
        float v = W1[j];
        __nv_bfloat16 h = __float2bfloat16(v);
        g_w1h[n * 256 + k] = h;
        g_w1l[n * 256 + k] = __float2bfloat16(v - __bfloat162float(h));
    } else {
        float v = W2[j];
        __nv_bfloat16 h = __float2bfloat16(v);
        g_w2h[n * 256 + k] = h;
        g_w2l[n * 256 + k] = __float2bfloat16(v - __bfloat162float(h));
    }
}

// ================= HMMA GEMM + fused attention-score epilogue =============
__device__ __forceinline__ void mma16816(float* c, const uint32_t* a, const uint32_t* b) {
    asm volatile(
        "mma.sync.aligned.m16n8k16.row.col.f32.bf16.bf16.f32 "
        "{%0,%1,%2,%3}, {%4,%5,%6,%7}, {%8,%9}, {%0,%1,%2,%3};"
        : "+f"(c[0]), "+f"(c[1]), "+f"(c[2]), "+f"(c[3])
        : "r"(a[0]), "r"(a[1]), "r"(a[2]), "r"(a[3]), "r"(b[0]), "r"(b[1]));
}

template <int H>
__global__ void __launch_bounds__(256, 1) gemm_mma(
    const float* __restrict__ A, const __nv_bfloat16* __restrict__ Bh,
    const __nv_bfloat16* __restrict__ Bl, __half* __restrict__ C, int M,
    const float* __restrict__ att_s, const float* __restrict__ att_d,
    float* __restrict__ o_asrc, float* __restrict__ o_adst) {
    extern __shared__ char sm[];
    uint32_t* Ahs = (uint32_t*)sm;                 // 64 KB
    uint32_t* Als = (uint32_t*)(sm + 65536);       // 64 KB

    int t = threadIdx.x;
    int warp = t >> 5, lane = t & 31;
    int g = lane >> 2, tg = lane & 3;
    int m0 = blockIdx.y * 128;
    int n0 = blockIdx.x * 128;

    // ---- stage A (fragment-permuted bf16 hi/lo) ----
    {
        int r0 = m0 + warp * 16 + g;
        int r1 = r0 + 8;
        bool ok0 = r0 < M, ok1 = r1 < M;
        const float* A0 = A + (size_t)r0 * 256 + 2 * tg;
        const float* A1 = A + (size_t)r1 * 256 + 2 * tg;
#pragma unroll
        for (int ks = 0; ks < 16; ks++) {
            float2 f0 = ok0 ? *(const float2*)(A0 + 16 * ks)     : make_float2(0.f, 0.f);
            float2 f1 = ok1 ? *(const float2*)(A1 + 16 * ks)     : make_float2(0.f, 0.f);
            float2 f2 = ok0 ? *(const float2*)(A0 + 16 * ks + 8) : make_float2(0.f, 0.f);
            float2 f3 = ok1 ? *(const float2*)(A1 + 16 * ks + 8) : make_float2(0.f, 0.f);
            float h0x = __bfloat162float(__float2bfloat16(f0.x));
            float h0y = __bfloat162float(__float2bfloat16(f0.y));
            float h1x = __bfloat162float(__float2bfloat16(f1.x));
            float h1y = __bfloat162float(__float2bfloat16(f1.y));
            float h2x = __bfloat162float(__float2bfloat16(f2.x));
            float h2y = __bfloat162float(__float2bfloat16(f2.y));
            float h3x = __bfloat162float(__float2bfloat16(f3.x));
            float h3y = __bfloat162float(__float2bfloat16(f3.y));
            int idx = ((warp * 16 + ks) * 32 + lane) * 4;
            uint4 hv = make_uint4(pack_bf2(f0.x, f0.y), pack_bf2(f1.x, f1.y),
                                  pack_bf2(f2.x, f2.y), pack_bf2(f3.x, f3.y));
            uint4 lv = make_uint4(pack_bf2(f0.x - h0x, f0.y - h0y),
                                  pack_bf2(f1.x - h1x, f1.y - h1y),
                                  pack_bf2(f2.x - h2x, f2.y - h2y),
                                  pack_bf2(f3.x - h3x, f3.y - h3y));
            *(uint4*)(Ahs + idx) = hv;
            *(uint4*)(Als + idx) = lv;
        }
    }
    __syncthreads();

    // ---- mainloop ----
    int wm = warp & 1;
    int wn = warp >> 1;
    float acc[4][4][4];
#pragma unroll
    for (int i = 0; i < 4; i++)
#pragma unroll
        for (int j = 0; j < 4; j++)
#pragma unroll
            for (int q = 0; q < 4; q++) acc[i][j][q] = 0.f;

    const __nv_bfloat16* Bbase[3] = { Bh, Bl, Bh };
#pragma unroll
    for (int pass = 0; pass < 3; pass++) {
        const uint32_t* Asm = (pass == 2) ? Als : Ahs;
        const __nv_bfloat16* Bg = Bbase[pass];
#pragma unroll 4
        for (int ks = 0; ks < 16; ks++) {
            uint32_t b[4][2];
#pragma unroll
            for (int fn = 0; fn < 4; fn++) {
                int n = n0 + wn * 32 + fn * 8 + g;
                const uint32_t* bp = (const uint32_t*)(Bg + (size_t)n * 256 + 16 * ks + 2 * tg);
                b[fn][0] = bp[0];
                b[fn][1] = bp[4];
            }
#pragma unroll
            for (int fm = 0; fm < 4; fm++) {
                int fm_g = wm * 4 + fm;
                uint4 av = *(const uint4*)(Asm + ((fm_g * 16 + ks) * 32 + lane) * 4);
                uint32_t a[4] = { av.x, av.y, av.z, av.w };
#pragma unroll
                for (int fn = 0; fn < 4; fn++)
                    mma16816(acc[fm][fn], a, b[fn]);
            }
        }
    }

    // ---- epilogue: store C as fp16 ----
#pragma unroll
    for (int fm = 0; fm < 4; fm++) {
        int r0 = m0 + wm * 64 + fm * 16 + g;
        int r1 = r0 + 8;
#pragma unroll
        for (int fn = 0; fn < 4; fn++) {
            int col = n0 + wn * 32 + fn * 8 + 2 * tg;
            if (r0 < M)
                *(__half2*)(C + (size_t)r0 * 256 + col) =
                    __floats2half2_rn(acc[fm][fn][0], acc[fm][fn][1]);
            if (r1 < M)
                *(__half2*)(C + (size_t)r1 * 256 + col) =
                    __floats2half2_rn(acc[fm][fn][2], acc[fm][fn][3]);
        }
    }

    // ---- epilogue: fused attention scores (fp32 accumulators) ----
    float2 as2[4], ad2[4];
#pragma unroll
    for (int fn = 0; fn < 4; fn++) {
        int col = n0 + wn * 32 + fn * 8 + 2 * tg;
        as2[fn] = *(const float2*)(att_s + col);
        ad2[fn] = *(const float2*)(att_d + col);
    }
    int head = (H == 4) ? ((n0 + wn * 32) >> 6) : 0;
#pragma unroll
    for (int fm = 0; fm < 4; fm++) {
        int r0 = m0 + wm * 64 + fm * 16 + g;
        int r1 = r0 + 8;
        float s0 = 0.f, d0 = 0.f, s1 = 0.f, d1 = 0.f;
#pragma unroll
        for (int fn = 0; fn < 4; fn++) {
            s0 += acc[fm][fn][0] * as2[fn].x + acc[fm][fn][1] * as2[fn].y;
            d0 += acc[fm][fn][0] * ad2[fn].x + acc[fm][fn][1] * ad2[fn].y;
            s1 += acc[fm][fn][2] * as2[fn].x + acc[fm][fn][3] * as2[fn].y;
            d1 += acc[fm][fn][2] * ad2[fn].x + acc[fm][fn][3] * ad2[fn].y;
        }
#pragma unroll
        for (int o = 1; o <= 2; o <<= 1) {
            s0 += __shfl_xor_sync(0xffffffffu, s0, o);
            d0 += __shfl_xor_sync(0xffffffffu, d0, o);
            s1 += __shfl_xor_sync(0xffffffffu, s1, o);
            d1 += __shfl_xor_sync(0xffffffffu, d1, o);
        }
        if (tg == 0) {
            if (r0 < M) {
                atomicAdd(&o_asrc[r0 * H + head], s0);
                atomicAdd(&o_adst[r0 * H + head], d0);
            }
            if (r1 < M) {
                atomicAdd(&o_asrc[r1 * H + head], s1);
                atomicAdd(&o_adst[r1 * H + head], d1);
            }
        }
    }
}

// ================= CSR build ==============================================
__global__ void zero_misc() {
    int i = blockIdx.x * 256 + threadIdx.x;
    if (i < N_NODES) { g_deg[i] = 0u; g_asrc2[i] = 0.f; g_adst2[i] = 0.f; }
    if (i < N_NODES * HEADS) { g_asrc[i] = 0.f; g_adst[i] = 0.f; }
    if (i < N_GRAPHS * FEAT) g_psum[i] = 0.f;
    if (i < N_GRAPHS) g_cnt[i] = 0.f;
}
__global__ void hist_plus(const int* __restrict__ dst, const int* __restrict__ batch) {
    int i = blockIdx.x * 256 + threadIdx.x;
    if (i < N_EDGES) atomicAdd(&g_deg[dst[i]], 1u);
    if (i < N_NODES) atomicAdd(&g_cnt[batch[i]], 1.0f);
}
__global__ void scan1() {
    __shared__ unsigned s[256];
    int t = threadIdx.x, i = blockIdx.x * 256 + t;
    unsigned v = (i < N_NODES) ? g_deg[i] : 0u;
    s[t] = v; __syncthreads();
#pragma unroll
    for (int o = 1; o < 256; o <<= 1) {
        unsigned u = (t >= o) ? s[t - o] : 0u;
        __syncthreads();
        s[t] += u; __syncthreads();
    }
    if (i < N_NODES) g_rowptr[i + 1] = s[t];
    if (t == 255) g_bsum[blockIdx.x] = s[255];
}
__global__ void scan2(int nb) {
    __shared__ unsigned s[256];
    int t = threadIdx.x;
    unsigned v = (t < nb) ? g_bsum[t] : 0u;
    s[t] = v; __syncthreads();
#pragma unroll
    for (int o = 1; o < 256; o <<= 1) {
        unsigned u = (t >= o) ? s[t - o] : 0u;
        __syncthreads();
        s[t] += u; __syncthreads();
    }
    if (t < nb) g_bsum[t] = s[t] - v;                // exclusive
}
__global__ void scan3() {
    int i = blockIdx.x * 256 + threadIdx.x;
    if (i >= N_NODES) return;
    unsigned f = g_rowptr[i + 1] + g_bsum[i >> 8];
    g_rowptr[i + 1] = f;
    g_cursor[i] = f - g_deg[i];
    if (i == 0) g_rowptr[0] = 0u;
}
__global__ void scatter(const int* __restrict__ src, const int* __restrict__ dst) {
    int e = blockIdx.x * 256 + threadIdx.x;
    if (e >= N_EDGES) return;
    unsigned p = atomicAdd(&g_cursor[dst[e]], 1u);
    g_csrc[p] = src[e];
}

// ================= fused single-pass GAT aggregation ======================
// out[w] = relu( (sum_e ex_e * h[src_e]) / (sum_e ex_e) + bias ), ex = exp(lrelu(score))
// 2-edge unrolled: both gather loads issued back-to-back (MLP=2).
template <int H>
__global__ void gat_gather(const __half* __restrict__ h, float* __restrict__ out,
                           const float* __restrict__ bias,
                           const float* __restrict__ v_asrc,
                           const float* __restrict__ v_adst) {
    int w = (blockIdx.x * blockDim.x + threadIdx.x) >> 5;
    int lane = threadIdx.x & 31;
    if (w >= N_NODES) return;
    int r0 = (int)g_rowptr[w], r1 = (int)g_rowptr[w + 1];
    int ch = lane * 8;
    int hh = (H == 4) ? (lane >> 3) : 0;
    float4 b0 = *(const float4*)(bias + ch);
    float4 b1 = *(const float4*)(bias + ch + 4);
    float4* op = (float4*)(out + (size_t)w * FEAT + ch);
    if (r0 == r1) {
        op[0] = make_float4(fmaxf(b0.x, 0.f), fmaxf(b0.y, 0.f), fmaxf(b0.z, 0.f), fmaxf(b0.w, 0.f));
        op[1] = make_float4(fmaxf(b1.x, 0.f), fmaxf(b1.y, 0.f), fmaxf(b1.z, 0.f), fmaxf(b1.w, 0.f));
        return;
    }
    float ad_h = v_adst[w * H + hh];
    float acc[8];
#pragma unroll
    for (int q = 0; q < 8; q++) acc[q] = 0.f;
    float sum_ex = 0.f;
    int e = r0;
    for (; e + 1 < r1; e += 2) {
        int sA = g_csrc[e], sB = g_csrc[e + 1];
        float aA = v_asrc[sA * H + hh];
        float aB = v_asrc[sB * H + hh];
        uint4 vA = *(const uint4*)(h + (size_t)sA * FEAT + ch);
        uint4 vB = *(const uint4*)(h + (size_t)sB * FEAT + ch);
        float exA = __expf(lrelu(aA + ad_h));
        float exB = __expf(lrelu(aB + ad_h));
        sum_ex += exA + exB;
        const __half2* hA = (const __half2*)&vA;
        const __half2* hB = (const __half2*)&vB;
#pragma unroll
        for (int q = 0; q < 4; q++) {
            float2 fA = __half22float2(hA[q]);
            float2 fB = __half22float2(hB[q]);
            acc[2 * q + 0] = fmaf(exA, fA.x, fmaf(exB, fB.x, acc[2 * q + 0]));
            acc[2 * q + 1] = fmaf(exA, fA.y, fmaf(exB, fB.y, acc[2 * q + 1]));
        }
    }
    if (e < r1) {
        int s = g_csrc[e];
        float ex = __expf(lrelu(v_asrc[s * H + hh] + ad_h));
        sum_ex += ex;
        uint4 v = *(const uint4*)(h + (size_t)s * FEAT + ch);
        const __half2* hv = (const __half2*)&v;
#pragma unroll
        for (int q = 0; q < 4; q++) {
            float2 f = __half22float2(hv[q]);
            acc[2 * q + 0] = fmaf(ex, f.x, acc[2 * q + 0]);
            acc[2 * q + 1] = fmaf(ex, f.y, acc[2 * q + 1]);
        }
    }
    float inv = 1.f / sum_ex;
    op[0] = make_float4(fmaxf(fmaf(acc[0], inv, b0.x), 0.f), fmaxf(fmaf(acc[1], inv, b0.y), 0.f),
                        fmaxf(fmaf(acc[2], inv, b0.z), 0.f), fmaxf(fmaf(acc[3], inv, b0.w), 0.f));
    op[1] = make_float4(fmaxf(fmaf(acc[4], inv, b1.x), 0.f), fmaxf(fmaf(acc[5], inv, b1.y), 0.f),
                        fmaxf(fmaf(acc[6], inv, b1.z), 0.f), fmaxf(fmaf(acc[7], inv, b1.w), 0.f));
}

// ================= pooling + fc ===========================================
#define NPB 128
__global__ void pool_sum(const float* __restrict__ out2, const int* __restrict__ batch) {
    int c = threadIdx.x;
    int n0 = blockIdx.x * NPB;
    int n1 = n0 + NPB; if (n1 > N_NODES) n1 = N_NODES;
    if (n0 >= N_NODES) return;
    float acc = 0.f;
    int curg = batch[n0];
    for (int n = n0; n < n1; n++) {
        int g = batch[n];
        if (g != curg) { atomicAdd(&g_psum[curg * FEAT + c], acc); acc = 0.f; curg = g; }
        acc += out2[(size_t)n * FEAT + c];
    }
    atomicAdd(&g_psum[curg * FEAT + c], acc);
}
__global__ void fc_out(const float* __restrict__ Wfc, const float* __restrict__ bfc,
                       float* __restrict__ out) {
    int g = blockIdx.x, c = threadIdx.x;
    __shared__ float p[FEAT];
    float inv = 1.f / fmaxf(g_cnt[g], 1.f);
    p[c] = g_psum[g * FEAT + c] * inv;
    __syncthreads();
    float acc = bfc[c];
#pragma unroll 8
    for (int k = 0; k < FEAT; k++) acc = fmaf(p[k], Wfc[k * FEAT + c], acc);
    out[g * FEAT + c] = fmaxf(acc, 0.f);
}

// ================= launch =================================================
extern "C" void kernel_launch(void* const* d_in, const int* in_sizes, int n_in,
                              void* d_out, int out_size) {
    const float* x        = (const float*)d_in[0];
    const int*   ei       = (const int*)  d_in[1];
    const int*   batch    = (const int*)  d_in[2];
    const float* W1       = (const float*)d_in[3];
    const float* att_src1 = (const float*)d_in[4];
    const float* att_dst1 = (const float*)d_in[5];
    const float* b1       = (const float*)d_in[6];
    const float* W2       = (const float*)d_in[7];
    const float* att_src2 = (const float*)d_in[8];
    const float* att_dst2 = (const float*)d_in[9];
    const float* b2       = (const float*)d_in[10];
    const float* Wfc      = (const float*)d_in[11];
    const float* bfc      = (const float*)d_in[12];
    float* out = (float*)d_out;

    const int* src = ei;
    const int* dst = ei + N_EDGES;

    float *pA, *pB, *pas1, *pad1, *pas2, *pad2;
    __half* ph;
    __nv_bfloat16 *w1h, *w1l, *w2h, *w2l;
    cudaGetSymbolAddress((void**)&pA, g_bufA);
    cudaGetSymbolAddress((void**)&pB, g_bufB);
    cudaGetSymbolAddress((void**)&ph, g_h16);
    cudaGetSymbolAddress((void**)&pas1, g_asrc);
    cudaGetSymbolAddress((void**)&pad1, g_adst);
    cudaGetSymbolAddress((void**)&pas2, g_asrc2);
    cudaGetSymbolAddress((void**)&pad2, g_adst2);
    cudaGetSymbolAddress((void**)&w1h, g_w1h);
    cudaGetSymbolAddress((void**)&w1l, g_w1l);
    cudaGetSymbolAddress((void**)&w2h, g_w2h);
    cudaGetSymbolAddress((void**)&w2l, g_w2l);

    const int DYN_SM = 131072;
    cudaFuncSetAttribute(gemm_mma<HEADS>, cudaFuncAttributeMaxDynamicSharedMemorySize, DYN_SM);
    cudaFuncSetAttribute(gemm_mma<1>,     cudaFuncAttributeMaxDynamicSharedMemorySize, DYN_SM);

    // lazily-created side stream + events (host resources only; device work is
    // identical on every call)
    static cudaStream_t s_side = nullptr;
    static cudaEvent_t evFork = nullptr, evJoin = nullptr;
    if (s_side == nullptr) {
        cudaStreamCreateWithFlags(&s_side, cudaStreamNonBlocking);
        cudaEventCreateWithFlags(&evFork, cudaEventDisableTiming);
        cudaEventCreateWithFlags(&evJoin, cudaEventDisableTiming);
    }

    int eBlocks    = (N_EDGES + 255) / 256;               // 3125
    int nhBlocks   = (N_NODES * HEADS + 255) / 256;       // 782
    int warpBlocks = (N_NODES * 32 + 255) / 256;          // 6250
    int nBlocks    = (N_NODES + 255) / 256;               // 196
    dim3 gemmGrid(2, (N_NODES + 127) / 128);              // (2, 391)

    // ---- init (main stream), then fork CSR build onto side stream ----
    zero_misc<<<nhBlocks, 256>>>();
    cudaEventRecord(evFork, 0);
    cudaStreamWaitEvent(s_side, evFork, 0);
    hist_plus<<<eBlocks, 256, 0, s_side>>>(dst, batch);
    scan1<<<nBlocks, 256, 0, s_side>>>();
    scan2<<<1, 256, 0, s_side>>>(nBlocks);
    scan3<<<nBlocks, 256, 0, s_side>>>();
    scatter<<<eBlocks, 256, 0, s_side>>>(src, dst);
    cudaEventRecord(evJoin, s_side);

    // ---- main stream: weights + GEMM1 (overlaps CSR build) ----
    conv_w2<<<512, 256>>>(W1, W2);
    gemm_mma<HEADS><<<gemmGrid, 256, DYN_SM>>>(x, w1h, w1l, ph, N_NODES,
                                               att_src1, att_dst1, pas1, pad1);

    // ---- join: gather needs CSR ----
    cudaStreamWaitEvent(0, evJoin, 0);
    gat_gather<HEADS><<<warpBlocks, 256>>>(ph, pB, b1, pas1, pad1);

    // ---- layer 2 (scores go to pre-zeroed second buffer set) ----
    gemm_mma<1><<<gemmGrid, 256, DYN_SM>>>(pB, w2h, w2l, ph, N_NODES,
                                           att_src2, att_dst2, pas2, pad2);
    gat_gather<1><<<warpBlocks, 256>>>(ph, pA, b2, pas2, pad2);

    // ---- pool + fc ----
    pool_sum<<<(N_NODES + NPB - 1) / NPB, 256>>>(pA, batch);
    fc_out<<<N_GRAPHS, FEAT>>>(Wfc, bfc, out);
}